// round 7
// baseline (speedup 1.0000x reference)
#include <cuda_runtime.h>
#include <cstdint>

#define BB 32
#define HH 56
#define HC 128
#define CC 256
#define PIX (HH*HH)          // 3136
#define EZ (BB*HC*PIX)       // 12845056
#define N1 (BB*PIX)          // 100352
#define OHH 112
#define OPIX (OHH*OHH)       // 12544
#define N2 (BB*OPIX)         // 401408
#define KW1 (257*9)          // 2313

typedef unsigned long long u64;

__device__ __align__(128) float g_z[EZ];        // conv1 out -> (in place) BEC output h
__device__ __align__(128) float g_wp[KW1*128];  // repacked w1: [ic*9+kk][oc]
__device__ double g_d1[128*8*2];                // BN1 partials (sum, sumsq)
__device__ double g_d2[256*8*2];                // BN2 partials
__device__ float g_m1[HC], g_rs1[HC];
__device__ float g_m2[CC], g_rs2[CC];

// packed fp32x2 FMA (Blackwell FFMA2 — only reachable via PTX)
__device__ __forceinline__ void ffma2(u64& d, u64 a, u64 b) {
  asm("fma.rn.f32x2 %0, %1, %2, %0;" : "+l"(d) : "l"(a), "l"(b));
}
__device__ __forceinline__ float2 unpk(u64 v) {
  float2 r;
  asm("mov.b64 {%0, %1}, %2;" : "=f"(r.x), "=f"(r.y) : "l"(v));
  return r;
}

// ---------------------------------------------------------------------------
// Kernel 0: repack w1 [oc][ic][kk] -> g_wp [ic*9+kk][oc]
// ---------------------------------------------------------------------------
__global__ __launch_bounds__(256) void repack_kernel(const float* __restrict__ w1) {
  int i = blockIdx.x * 256 + threadIdx.x;
  if (i < KW1 * 128) {
    int oc = i & 127, ickk = i >> 7;
    g_wp[ickk * 128 + oc] = w1[oc * KW1 + ickk];
  }
}

// ---------------------------------------------------------------------------
// Kernel 1: conv 3x3 s1 p1, packed-FFMA2 over oc pairs.
// Tile 128 oc x (8x16) px, 256 threads, (4 ocpair) x 8 px microtile.
// Input staged duplicated {v,v}; weights read as natural b64 oc-pairs.
// ---------------------------------------------------------------------------
__global__ __launch_bounds__(256) void conv1_kernel(
    const float* __restrict__ x, const float* __restrict__ nu,
    const float* __restrict__ b1) {
  __shared__ float sInD[2][180 * 2];   // duplicated input pairs
  __shared__ float4 sW[2][288];        // [kk][oc] floats (staged as float4)
  const int t = threadIdx.x;
  const int bx = blockIdx.x, by = blockIdx.y, b = blockIdx.z;
  const float nf = nu[0] * 0.5f;

  const int og = t >> 4;
  const int p  = t & 15;
  const int row = p >> 1;
  const int cbase = (p & 1) * 8;
  const int r0 = by * 8, c0 = bx * 16;

  const int lr = t / 18, lc = t % 18;
  const int gy = r0 - 1 + lr, gx = c0 - 1 + lc;
  const bool inb = (t < 180) && (gy >= 0) && (gy < HH) && (gx >= 0) && (gx < HH);
  const long xoff = ((long)b * 256) * PIX + (long)gy * HH + gx;

  u64 acc2[32];   // [ocpair j<4][px i<8], lanes = (oc=og*8+2j, oc+1)
#pragma unroll
  for (int i = 0; i < 32; ++i) acc2[i] = 0ULL;

  const float4* wp4 = (const float4*)g_wp;

  // prologue: stage ic=0
  {
    float v = 0.f;
    if (inb) v = x[xoff];
    float4 wa = wp4[t];
    float4 wb;
    if (t < 32) wb = wp4[256 + t];
    if (t < 180) *(float2*)&sInD[0][2 * t] = make_float2(v, v);
    sW[0][t] = wa;
    if (t < 32) sW[0][256 + t] = wb;
  }
  __syncthreads();

  float pin = 0.f;
  float4 pwa, pwb;

  for (int ic = 0; ic < 257; ++ic) {
    const int cur = ic & 1, nxt = cur ^ 1;
    if (ic < 256) {
      const int icn = ic + 1;
      pin = 0.f;
      if (inb) pin = (icn < 256) ? x[xoff + (long)icn * PIX] : nf;
      pwa = wp4[icn * 288 + t];
      if (t < 32) pwb = wp4[icn * 288 + 256 + t];
    }
    const float* wf = (const float*)sW[cur];
#pragma unroll
    for (int kh = 0; kh < 3; ++kh) {
      u64 ivd[10];
#pragma unroll
      for (int j = 0; j < 10; ++j)
        ivd[j] = *(const u64*)&sInD[cur][2 * ((row + kh) * 18 + cbase + j)];
#pragma unroll
      for (int kw = 0; kw < 3; ++kw) {
        const int kk = kh * 3 + kw;
        u64 w2[4];
#pragma unroll
        for (int j = 0; j < 4; ++j)
          w2[j] = *(const u64*)&wf[kk * 128 + og * 8 + 2 * j];
#pragma unroll
        for (int j = 0; j < 4; ++j)
#pragma unroll
          for (int i = 0; i < 8; ++i)
            ffma2(acc2[j * 8 + i], w2[j], ivd[kw + i]);
      }
    }
    if (ic < 256) {
      if (t < 180) *(float2*)&sInD[nxt][2 * t] = make_float2(pin, pin);
      sW[nxt][t] = pwa;
      if (t < 32) sW[nxt][256 + t] = pwb;
    }
    __syncthreads();
  }

  if (c0 + cbase < HH) {
#pragma unroll
    for (int j = 0; j < 4; ++j) {
      const int oc0 = og * 8 + 2 * j;
      const float b0 = b1[oc0], b1v = b1[oc0 + 1];
      float lo[8], hi[8];
#pragma unroll
      for (int i = 0; i < 8; ++i) {
        float2 u = unpk(acc2[j * 8 + i]);
        lo[i] = u.x + b0;
        hi[i] = u.y + b1v;
      }
      float* d0 = g_z + ((b * 128 + oc0) * HH + r0 + row) * HH + c0 + cbase;
      float* d1 = d0 + PIX;
      ((float4*)d0)[0] = make_float4(lo[0], lo[1], lo[2], lo[3]);
      ((float4*)d0)[1] = make_float4(lo[4], lo[5], lo[6], lo[7]);
      ((float4*)d1)[0] = make_float4(hi[0], hi[1], hi[2], hi[3]);
      ((float4*)d1)[1] = make_float4(hi[4], hi[5], hi[6], hi[7]);
    }
  }
}

// ---------------------------------------------------------------------------
// Kernel 2a: BN1 partial stats — grid (128 ch, 8 slices), 4 batches/slice
// ---------------------------------------------------------------------------
__global__ __launch_bounds__(256) void stats1a_kernel() {
  const int c = blockIdx.x, sl = blockIdx.y, t = threadIdx.x;
  double s = 0.0, q = 0.0;
  for (int bb = sl * 4; bb < sl * 4 + 4; ++bb) {
    const float4* p = (const float4*)(g_z + (bb * 128 + c) * PIX);
    for (int i = t; i < PIX / 4; i += 256) {
      float4 v = p[i];
      s += (double)v.x + v.y + v.z + v.w;
      q += (double)v.x * v.x + (double)v.y * v.y +
           (double)v.z * v.z + (double)v.w * v.w;
    }
  }
  __shared__ double ss[256], sq[256];
  ss[t] = s; sq[t] = q;
  __syncthreads();
  for (int o = 128; o > 0; o >>= 1) {
    if (t < o) { ss[t] += ss[t + o]; sq[t] += sq[t + o]; }
    __syncthreads();
  }
  if (t == 0) {
    g_d1[(c * 8 + sl) * 2 + 0] = ss[0];
    g_d1[(c * 8 + sl) * 2 + 1] = sq[0];
  }
}

__global__ __launch_bounds__(128) void reduce1_kernel() {
  const int c = threadIdx.x;
  double s = 0.0, q = 0.0;
#pragma unroll
  for (int sl = 0; sl < 8; ++sl) {
    s += g_d1[(c * 8 + sl) * 2 + 0];
    q += g_d1[(c * 8 + sl) * 2 + 1];
  }
  double m   = s / N1;
  double var = q / N1 - m * m;
  g_m1[c]  = (float)m;
  g_rs1[c] = rsqrtf((float)var + 1e-5f);
}

// ---------------------------------------------------------------------------
// Threefry2x32, key (0,42), partitionable draw: x0=0, x1=j, out = o0^o1.
// ---------------------------------------------------------------------------
__device__ __forceinline__ unsigned tf_xor(unsigned j) {
  const unsigned ks0 = 0u, ks1 = 42u, ks2 = 0x1BD11BDAu ^ 42u;
  unsigned x0 = 0u + ks0;
  unsigned x1 = j  + ks1;
#define TFRND(r) { x0 += x1; x1 = __funnelshift_l(x1, x1, r); x1 ^= x0; }
  TFRND(13) TFRND(15) TFRND(26) TFRND(6)
  x0 += ks1; x1 += ks2 + 1u;
  TFRND(17) TFRND(29) TFRND(16) TFRND(24)
  x0 += ks2; x1 += ks0 + 2u;
  TFRND(13) TFRND(15) TFRND(26) TFRND(6)
  x0 += ks0; x1 += ks1 + 3u;
  TFRND(17) TFRND(29) TFRND(16) TFRND(24)
  x0 += ks1; x1 += ks2 + 4u;
  TFRND(13) TFRND(15) TFRND(26) TFRND(6)
  x0 += ks2; x1 += ks0 + 5u;
#undef TFRND
  return x0 ^ x1;
}

// ---------------------------------------------------------------------------
// Kernel 3: BN1 apply + sigmoid + quantize + BEC (in place on g_z)
// ---------------------------------------------------------------------------
__global__ __launch_bounds__(256) void bec_kernel(
    const float* __restrict__ nu, const float* __restrict__ g1,
    const float* __restrict__ be1) {
  const int e = blockIdx.x * 256 + threadIdx.x;
  const int c = (e / PIX) & 127;
  const float z = g_z[e];
  float tt = (z - g_m1[c]) * g_rs1[c] * g1[c] + be1[c];
  float s  = 0.5f * tanhf(0.5f * tt) + 0.5f;
  float r  = rintf(s * 256.0f);
  if (r >= 256.0f) r -= 256.0f;
  const unsigned xb = (unsigned)r;

  const float q = 1.0f - nu[0] * 0.5f;
  unsigned mask = 0u;
#pragma unroll
  for (int k = 0; k < 8; ++k) {
    unsigned bits = tf_xor((unsigned)(k * EZ + e));
    float u = __uint_as_float((bits >> 9) | 0x3f800000u) - 1.0f;
    if (u < q) mask |= (1u << k);
  }
  float outv = ((float)(xb & mask) + (255.0f - (float)mask) / 2.0f) / 255.0f;
  g_z[e] = outv;
}

// ---------------------------------------------------------------------------
// Kernel 4: ConvTranspose2d(k2,s2) as 4-tap GEMM, packed-FFMA2 over px pairs.
// Tile 64 px x 64 oc x 4 taps; 256 threads; (2c x 4 pxpair x 4 tap) acc pairs.
// ---------------------------------------------------------------------------
__global__ __launch_bounds__(256) void dec_kernel(
    const float* __restrict__ w4, const float* __restrict__ b4,
    float* __restrict__ out) {
  __shared__ float wsD[16 * 64 * 4 * 2];   // [hh][cl][tap] duplicated pairs: 32KB
  __shared__ float4 hs4[16 * 16];          // [hh][px/4]: 4KB
  const int t = threadIdx.x;
  const int bp = blockIdx.x;
  const int b = bp / 49;
  const int pixb = (bp % 49) * 64;
  const int cb = blockIdx.y * 64;
  const int pgrp = t & 7;
  const int cgrp = t >> 3;

  u64 a2[32];   // [cc2][pxpair4][tap4], lanes = (px even, px odd)
#pragma unroll
  for (int i = 0; i < 32; ++i) a2[i] = 0ULL;

  const float4* w44 = (const float4*)w4;
  const float4* gz4 = (const float4*)g_z;
  const float* hsf = (const float*)hs4;

  for (int hc0 = 0; hc0 < 128; hc0 += 16) {
    __syncthreads();
#pragma unroll
    for (int i = 0; i < 4; ++i) {
      int idx = t + i * 256;
      int hh = idx >> 6, cl = idx & 63;
      float4 w = w44[(hc0 + hh) * 256 + cb + cl];
      float4* d = (float4*)&wsD[(hh * 64 + cl) * 8];
      d[0] = make_float4(w.x, w.x, w.y, w.y);
      d[1] = make_float4(w.z, w.z, w.w, w.w);
    }
    {
      int hh = t >> 4, p4 = t & 15;
      hs4[t] = gz4[((b * 128 + hc0 + hh) * PIX + pixb) / 4 + p4];
    }
    __syncthreads();
#pragma unroll
    for (int hh = 0; hh < 16; ++hh) {
      u64 h2[4];
#pragma unroll
      for (int pr = 0; pr < 4; ++pr)
        h2[pr] = *(const u64*)&hsf[hh * 64 + pgrp * 8 + 2 * pr];
      u64 wv[8];
#pragma unroll
      for (int cc = 0; cc < 2; ++cc)
#pragma unroll
        for (int tap = 0; tap < 4; ++tap)
          wv[cc * 4 + tap] =
              *(const u64*)&wsD[(hh * 64 + cgrp * 2 + cc) * 8 + tap * 2];
#pragma unroll
      for (int cc = 0; cc < 2; ++cc)
#pragma unroll
        for (int pr = 0; pr < 4; ++pr)
#pragma unroll
          for (int tap = 0; tap < 4; ++tap)
            ffma2(a2[cc * 16 + pr * 4 + tap], wv[cc * 4 + tap], h2[pr]);
    }
  }

#pragma unroll
  for (int cc = 0; cc < 2; ++cc) {
    const int c = cb + cgrp * 2 + cc;
    const float bb = b4[c];
#pragma unroll
    for (int pr = 0; pr < 4; ++pr) {
      float2 t0 = unpk(a2[cc * 16 + pr * 4 + 0]);
      float2 t1 = unpk(a2[cc * 16 + pr * 4 + 1]);
      float2 t2 = unpk(a2[cc * 16 + pr * 4 + 2]);
      float2 t3 = unpk(a2[cc * 16 + pr * 4 + 3]);
      const int px0 = pixb + pgrp * 8 + 2 * pr;
      {
        const int ih = px0 / HH, iw = px0 % HH;
        float* dst = out + ((b * 256 + c) * OHH + 2 * ih) * OHH + 2 * iw;
        *(float2*)dst = make_float2(t0.x + bb, t1.x + bb);
        *(float2*)(dst + OHH) = make_float2(t2.x + bb, t3.x + bb);
      }
      {
        const int px1 = px0 + 1;
        const int ih = px1 / HH, iw = px1 % HH;
        float* dst = out + ((b * 256 + c) * OHH + 2 * ih) * OHH + 2 * iw;
        *(float2*)dst = make_float2(t0.y + bb, t1.y + bb);
        *(float2*)(dst + OHH) = make_float2(t2.y + bb, t3.y + bb);
      }
    }
  }
}

// ---------------------------------------------------------------------------
// Kernel 5a: BN2 partial stats — grid (256 ch, 8 slices), 4 batches/slice
// ---------------------------------------------------------------------------
__global__ __launch_bounds__(256) void stats2a_kernel(const float* __restrict__ out) {
  const int c = blockIdx.x, sl = blockIdx.y, t = threadIdx.x;
  double s = 0.0, q = 0.0;
  for (int bb = sl * 4; bb < sl * 4 + 4; ++bb) {
    const float4* p = (const float4*)(out + (bb * 256 + c) * OPIX);
    for (int i = t; i < OPIX / 4; i += 256) {
      float4 v = p[i];
      s += (double)v.x + v.y + v.z + v.w;
      q += (double)v.x * v.x + (double)v.y * v.y +
           (double)v.z * v.z + (double)v.w * v.w;
    }
  }
  __shared__ double ss[256], sq[256];
  ss[t] = s; sq[t] = q;
  __syncthreads();
  for (int o = 128; o > 0; o >>= 1) {
    if (t < o) { ss[t] += ss[t + o]; sq[t] += sq[t + o]; }
    __syncthreads();
  }
  if (t == 0) {
    g_d2[(c * 8 + sl) * 2 + 0] = ss[0];
    g_d2[(c * 8 + sl) * 2 + 1] = sq[0];
  }
}

__global__ __launch_bounds__(256) void reduce2_kernel() {
  const int c = threadIdx.x;
  double s = 0.0, q = 0.0;
#pragma unroll
  for (int sl = 0; sl < 8; ++sl) {
    s += g_d2[(c * 8 + sl) * 2 + 0];
    q += g_d2[(c * 8 + sl) * 2 + 1];
  }
  double m   = s / N2;
  double var = q / N2 - m * m;
  g_m2[c]  = (float)m;
  g_rs2[c] = rsqrtf((float)var + 1e-5f);
}

// ---------------------------------------------------------------------------
// Kernel 6: BN2 apply + relu, in place on d_out
// ---------------------------------------------------------------------------
__global__ __launch_bounds__(256) void bn2_kernel(
    const float* __restrict__ g2, const float* __restrict__ be2,
    float* __restrict__ out) {
  const int i = blockIdx.x * 256 + threadIdx.x;
  const int c = (i / (OPIX / 4)) & 255;
  float4 v = ((float4*)out)[i];
  const float m = g_m2[c], rs = g_rs2[c], gg = g2[c], bb = be2[c];
  v.x = fmaxf((v.x - m) * rs * gg + bb, 0.f);
  v.y = fmaxf((v.y - m) * rs * gg + bb, 0.f);
  v.z = fmaxf((v.z - m) * rs * gg + bb, 0.f);
  v.w = fmaxf((v.w - m) * rs * gg + bb, 0.f);
  ((float4*)out)[i] = v;
}

// ---------------------------------------------------------------------------
extern "C" void kernel_launch(void* const* d_in, const int* in_sizes, int n_in,
                              void* d_out, int out_size) {
  const float* x   = (const float*)d_in[0];
  const float* nu  = (const float*)d_in[1];
  const float* w1  = (const float*)d_in[2];
  const float* b1  = (const float*)d_in[3];
  const float* g1  = (const float*)d_in[4];
  const float* be1 = (const float*)d_in[5];
  const float* w4  = (const float*)d_in[6];
  const float* b4  = (const float*)d_in[7];
  const float* g2  = (const float*)d_in[8];
  const float* be2 = (const float*)d_in[9];
  float* out = (float*)d_out;

  repack_kernel<<<(KW1 * 128 + 255) / 256, 256>>>(w1);
  conv1_kernel<<<dim3(4, 7, 32), 256>>>(x, nu, b1);
  stats1a_kernel<<<dim3(128, 8), 256>>>();
  reduce1_kernel<<<1, 128>>>();
  bec_kernel<<<EZ / 256, 256>>>(nu, g1, be1);
  dec_kernel<<<dim3(32 * 49, 4), 256>>>(w4, b4, out);
  stats2a_kernel<<<dim3(256, 8), 256>>>(out);
  reduce2_kernel<<<1, 256>>>();
  bn2_kernel<<<out_size / 4 / 256, 256>>>(g2, be2, out);
}

// round 8
// speedup vs baseline: 1.0995x; 1.0995x over previous
#include <cuda_runtime.h>
#include <cstdint>

#define BB 32
#define HH 56
#define HC 128
#define CC 256
#define PIX (HH*HH)          // 3136
#define EZ (BB*HC*PIX)       // 12845056
#define N1 (BB*PIX)          // 100352
#define OHH 112
#define OPIX (OHH*OHH)       // 12544
#define N2 (BB*OPIX)         // 401408
#define KW1 (257*9)          // 2313

__device__ __align__(128) float g_z[EZ];        // conv1 out -> (in place) BEC output h
__device__ __align__(128) float g_wp[KW1*128];  // repacked w1: [ic*9+kk][oc]
__device__ double g_d1[128*8*2];                // BN1 partials (sum, sumsq)
__device__ double g_d2[256*8*2];                // BN2 partials
__device__ float g_m1[HC], g_rs1[HC];
__device__ float g_m2[CC], g_rs2[CC];

// ---------------------------------------------------------------------------
// Kernel 0: repack w1 [oc][ic][kk] -> g_wp [ic*9+kk][oc]
// ---------------------------------------------------------------------------
__global__ __launch_bounds__(256) void repack_kernel(const float* __restrict__ w1) {
  int i = blockIdx.x * 256 + threadIdx.x;
  if (i < KW1 * 128) {
    int oc = i & 127, ickk = i >> 7;
    g_wp[ickk * 128 + oc] = w1[oc * KW1 + ickk];
  }
}

// ---------------------------------------------------------------------------
// Kernel 1: conv 3x3 s1 p1, 257 in-ch (ch256 = noise const), 128 out-ch.
// Tile: 128 oc x (8 rows x 14 cols) px — 56 = 4*14, ZERO tile waste.
// 256 threads = 16 oc-groups x (8 rows x 2 col-segments of 7 px).
// Double-buffered smem, one __syncthreads per ic.  8 oc x 7 px microtile.
// ---------------------------------------------------------------------------
__global__ __launch_bounds__(256) void conv1_kernel(
    const float* __restrict__ x, const float* __restrict__ nu,
    const float* __restrict__ b1) {
  __shared__ float sIn[2][160];    // 10 rows x 16 cols halo
  __shared__ float4 sW[2][288];    // 9 kk x 128 oc
  const int t = threadIdx.x;
  const int bx = blockIdx.x, by = blockIdx.y, b = blockIdx.z;
  const float nf = nu[0] * 0.5f;

  const int og = t >> 4;             // oc group: oc base = og*8
  const int p  = t & 15;
  const int row = p >> 1;            // 0..7
  const int cbase = (p & 1) * 7;     // 0 or 7
  const int r0 = by * 8, c0 = bx * 14;

  // halo loader: threads 0..159 cover 10 x 16
  const int lr = t >> 4, lc = t & 15;
  const int gy = r0 - 1 + lr, gx = c0 - 1 + lc;
  const bool inb = (t < 160) && (gy >= 0) && (gy < HH) && (gx >= 0) && (gx < HH);
  const long xoff = ((long)b * 256) * PIX + (long)gy * HH + gx;

  float acc[56];                     // [ocl 8][px 7]
#pragma unroll
  for (int i = 0; i < 56; ++i) acc[i] = 0.f;

  const float4* wp4 = (const float4*)g_wp;

  // prologue: stage ic=0 into buffer 0
  {
    float v = 0.f;
    if (inb) v = x[xoff];
    float4 wa = wp4[t];
    float4 wb;
    if (t < 32) wb = wp4[256 + t];
    if (t < 160) sIn[0][t] = v;
    sW[0][t] = wa;
    if (t < 32) sW[0][256 + t] = wb;
  }
  __syncthreads();

  float pin = 0.f;
  float4 pwa, pwb;

  for (int ic = 0; ic < 257; ++ic) {
    const int cur = ic & 1, nxt = cur ^ 1;
    // prefetch ic+1 into registers (overlaps compute)
    if (ic < 256) {
      const int icn = ic + 1;
      pin = 0.f;
      if (inb) pin = (icn < 256) ? x[xoff + (long)icn * PIX] : nf;
      pwa = wp4[icn * 288 + t];
      if (t < 32) pwb = wp4[icn * 288 + 256 + t];
    }
    // compute current ic
#pragma unroll
    for (int kh = 0; kh < 3; ++kh) {
      float inr[9];
#pragma unroll
      for (int j = 0; j < 9; ++j) inr[j] = sIn[cur][(row + kh) * 16 + cbase + j];
#pragma unroll
      for (int kw = 0; kw < 3; ++kw) {
        const int kk = kh * 3 + kw;
        const float4 wa = sW[cur][kk * 32 + og * 2];
        const float4 wb = sW[cur][kk * 32 + og * 2 + 1];
#pragma unroll
        for (int j = 0; j < 7; ++j) {
          const float iv = inr[kw + j];
          acc[0 * 7 + j] += wa.x * iv;
          acc[1 * 7 + j] += wa.y * iv;
          acc[2 * 7 + j] += wa.z * iv;
          acc[3 * 7 + j] += wa.w * iv;
          acc[4 * 7 + j] += wb.x * iv;
          acc[5 * 7 + j] += wb.y * iv;
          acc[6 * 7 + j] += wb.z * iv;
          acc[7 * 7 + j] += wb.w * iv;
        }
      }
    }
    // store prefetched ic+1 into buffer nxt
    if (ic < 256) {
      if (t < 160) sIn[nxt][t] = pin;
      sW[nxt][t] = pwa;
      if (t < 32) sW[nxt][256 + t] = pwb;
    }
    __syncthreads();
  }

  // epilogue: +bias, store 7 px per oc (no predicate — exact tiling)
#pragma unroll
  for (int ocl = 0; ocl < 8; ++ocl) {
    const int oc = og * 8 + ocl;
    const float bb = b1[oc];
    float* dst = g_z + ((b * 128 + oc) * HH + r0 + row) * HH + c0 + cbase;
#pragma unroll
    for (int j = 0; j < 7; ++j) dst[j] = acc[ocl * 7 + j] + bb;
  }
}

// ---------------------------------------------------------------------------
// Kernel 2a: BN1 partial stats — grid (128 ch, 8 slices), 4 batches/slice
// ---------------------------------------------------------------------------
__global__ __launch_bounds__(256) void stats1a_kernel() {
  const int c = blockIdx.x, sl = blockIdx.y, t = threadIdx.x;
  double s = 0.0, q = 0.0;
  for (int bb = sl * 4; bb < sl * 4 + 4; ++bb) {
    const float4* p = (const float4*)(g_z + (bb * 128 + c) * PIX);
    for (int i = t; i < PIX / 4; i += 256) {
      float4 v = p[i];
      s += (double)v.x + v.y + v.z + v.w;
      q += (double)v.x * v.x + (double)v.y * v.y +
           (double)v.z * v.z + (double)v.w * v.w;
    }
  }
  __shared__ double ss[256], sq[256];
  ss[t] = s; sq[t] = q;
  __syncthreads();
  for (int o = 128; o > 0; o >>= 1) {
    if (t < o) { ss[t] += ss[t + o]; sq[t] += sq[t + o]; }
    __syncthreads();
  }
  if (t == 0) {
    g_d1[(c * 8 + sl) * 2 + 0] = ss[0];
    g_d1[(c * 8 + sl) * 2 + 1] = sq[0];
  }
}

__global__ __launch_bounds__(128) void reduce1_kernel() {
  const int c = threadIdx.x;
  double s = 0.0, q = 0.0;
#pragma unroll
  for (int sl = 0; sl < 8; ++sl) {
    s += g_d1[(c * 8 + sl) * 2 + 0];
    q += g_d1[(c * 8 + sl) * 2 + 1];
  }
  double m   = s / N1;
  double var = q / N1 - m * m;
  g_m1[c]  = (float)m;
  g_rs1[c] = rsqrtf((float)var + 1e-5f);
}

// ---------------------------------------------------------------------------
// Threefry2x32, key (0,42), partitionable draw: x0=0, x1=j, out = o0^o1.
// ---------------------------------------------------------------------------
__device__ __forceinline__ unsigned tf_xor(unsigned j) {
  const unsigned ks0 = 0u, ks1 = 42u, ks2 = 0x1BD11BDAu ^ 42u;
  unsigned x0 = 0u + ks0;
  unsigned x1 = j  + ks1;
#define TFRND(r) { x0 += x1; x1 = __funnelshift_l(x1, x1, r); x1 ^= x0; }
  TFRND(13) TFRND(15) TFRND(26) TFRND(6)
  x0 += ks1; x1 += ks2 + 1u;
  TFRND(17) TFRND(29) TFRND(16) TFRND(24)
  x0 += ks2; x1 += ks0 + 2u;
  TFRND(13) TFRND(15) TFRND(26) TFRND(6)
  x0 += ks0; x1 += ks1 + 3u;
  TFRND(17) TFRND(29) TFRND(16) TFRND(24)
  x0 += ks1; x1 += ks2 + 4u;
  TFRND(13) TFRND(15) TFRND(26) TFRND(6)
  x0 += ks2; x1 += ks0 + 5u;
#undef TFRND
  return x0 ^ x1;
}

// ---------------------------------------------------------------------------
// Kernel 3: BN1 apply + sigmoid + quantize + BEC (in place on g_z)
// ---------------------------------------------------------------------------
__global__ __launch_bounds__(256) void bec_kernel(
    const float* __restrict__ nu, const float* __restrict__ g1,
    const float* __restrict__ be1) {
  const int e = blockIdx.x * 256 + threadIdx.x;
  const int c = (e / PIX) & 127;
  const float z = g_z[e];
  float tt = (z - g_m1[c]) * g_rs1[c] * g1[c] + be1[c];
  float s  = 0.5f * tanhf(0.5f * tt) + 0.5f;
  float r  = rintf(s * 256.0f);
  if (r >= 256.0f) r -= 256.0f;
  const unsigned xb = (unsigned)r;

  const float q = 1.0f - nu[0] * 0.5f;
  unsigned mask = 0u;
#pragma unroll
  for (int k = 0; k < 8; ++k) {
    unsigned bits = tf_xor((unsigned)(k * EZ + e));
    float u = __uint_as_float((bits >> 9) | 0x3f800000u) - 1.0f;
    if (u < q) mask |= (1u << k);
  }
  float outv = ((float)(xb & mask) + (255.0f - (float)mask) / 2.0f) / 255.0f;
  g_z[e] = outv;
}

// ---------------------------------------------------------------------------
// Kernel 4: ConvTranspose2d(k2,s2) as 4-tap GEMM (round-6 FFMA version).
// Tile: 64 px x 64 oc x 4 taps; 256 threads, 8px x 2c x 4tap = 64 acc each.
// ---------------------------------------------------------------------------
__global__ __launch_bounds__(256) void dec_kernel(
    const float* __restrict__ w4, const float* __restrict__ b4,
    float* __restrict__ out) {
  __shared__ float4 ws4[16 * 64];   // [hc-chunk][c-local] -> 4 taps
  __shared__ float4 hs4[16 * 16];   // [hc-chunk][px/4]
  const int t = threadIdx.x;
  const int bp = blockIdx.x;
  const int b = bp / 49;
  const int pixb = (bp % 49) * 64;
  const int cb = blockIdx.y * 64;
  const int pgrp = t & 7;
  const int cgrp = t >> 3;

  float acc[64];
#pragma unroll
  for (int i = 0; i < 64; ++i) acc[i] = 0.f;

  const float4* w44 = (const float4*)w4;
  const float4* gz4 = (const float4*)g_z;

  for (int hc0 = 0; hc0 < 128; hc0 += 16) {
    __syncthreads();
#pragma unroll
    for (int i = 0; i < 4; ++i) {
      int idx = t + i * 256;
      int hh = idx >> 6, cl = idx & 63;
      ws4[idx] = w44[(hc0 + hh) * 256 + cb + cl];
    }
    {
      int hh = t >> 4, p4 = t & 15;
      hs4[t] = gz4[((b * 128 + hc0 + hh) * PIX + pixb) / 4 + p4];
    }
    __syncthreads();
#pragma unroll
    for (int hh = 0; hh < 16; ++hh) {
      const float4 h0 = hs4[hh * 16 + pgrp * 2];
      const float4 h1 = hs4[hh * 16 + pgrp * 2 + 1];
      const float4 wa = ws4[hh * 64 + cgrp * 2];
      const float4 wb = ws4[hh * 64 + cgrp * 2 + 1];
      const float hv[8] = {h0.x, h0.y, h0.z, h0.w, h1.x, h1.y, h1.z, h1.w};
#pragma unroll
      for (int pp = 0; pp < 8; ++pp) {
        acc[pp * 4 + 0] += hv[pp] * wa.x;
        acc[pp * 4 + 1] += hv[pp] * wa.y;
        acc[pp * 4 + 2] += hv[pp] * wa.z;
        acc[pp * 4 + 3] += hv[pp] * wa.w;
        acc[32 + pp * 4 + 0] += hv[pp] * wb.x;
        acc[32 + pp * 4 + 1] += hv[pp] * wb.y;
        acc[32 + pp * 4 + 2] += hv[pp] * wb.z;
        acc[32 + pp * 4 + 3] += hv[pp] * wb.w;
      }
    }
  }

#pragma unroll
  for (int cc = 0; cc < 2; ++cc) {
    const int c = cb + cgrp * 2 + cc;
    const float bb = b4[c];
#pragma unroll
    for (int pp = 0; pp < 8; ++pp) {
      const int pix = pixb + pgrp * 8 + pp;
      const int ih = pix / HH, iw = pix % HH;
      float* dst = out + ((b * 256 + c) * OHH + 2 * ih) * OHH + 2 * iw;
      float2 top = {acc[cc * 32 + pp * 4 + 0] + bb, acc[cc * 32 + pp * 4 + 1] + bb};
      float2 bot = {acc[cc * 32 + pp * 4 + 2] + bb, acc[cc * 32 + pp * 4 + 3] + bb};
      *(float2*)dst = top;
      *(float2*)(dst + OHH) = bot;
    }
  }
}

// ---------------------------------------------------------------------------
// Kernel 5a: BN2 partial stats — grid (256 ch, 8 slices), 4 batches/slice
// ---------------------------------------------------------------------------
__global__ __launch_bounds__(256) void stats2a_kernel(const float* __restrict__ out) {
  const int c = blockIdx.x, sl = blockIdx.y, t = threadIdx.x;
  double s = 0.0, q = 0.0;
  for (int bb = sl * 4; bb < sl * 4 + 4; ++bb) {
    const float4* p = (const float4*)(out + (bb * 256 + c) * OPIX);
    for (int i = t; i < OPIX / 4; i += 256) {
      float4 v = p[i];
      s += (double)v.x + v.y + v.z + v.w;
      q += (double)v.x * v.x + (double)v.y * v.y +
           (double)v.z * v.z + (double)v.w * v.w;
    }
  }
  __shared__ double ss[256], sq[256];
  ss[t] = s; sq[t] = q;
  __syncthreads();
  for (int o = 128; o > 0; o >>= 1) {
    if (t < o) { ss[t] += ss[t + o]; sq[t] += sq[t + o]; }
    __syncthreads();
  }
  if (t == 0) {
    g_d2[(c * 8 + sl) * 2 + 0] = ss[0];
    g_d2[(c * 8 + sl) * 2 + 1] = sq[0];
  }
}

__global__ __launch_bounds__(256) void reduce2_kernel() {
  const int c = threadIdx.x;
  double s = 0.0, q = 0.0;
#pragma unroll
  for (int sl = 0; sl < 8; ++sl) {
    s += g_d2[(c * 8 + sl) * 2 + 0];
    q += g_d2[(c * 8 + sl) * 2 + 1];
  }
  double m   = s / N2;
  double var = q / N2 - m * m;
  g_m2[c]  = (float)m;
  g_rs2[c] = rsqrtf((float)var + 1e-5f);
}

// ---------------------------------------------------------------------------
// Kernel 6: BN2 apply + relu, in place on d_out
// ---------------------------------------------------------------------------
__global__ __launch_bounds__(256) void bn2_kernel(
    const float* __restrict__ g2, const float* __restrict__ be2,
    float* __restrict__ out) {
  const int i = blockIdx.x * 256 + threadIdx.x;
  const int c = (i / (OPIX / 4)) & 255;
  float4 v = ((float4*)out)[i];
  const float m = g_m2[c], rs = g_rs2[c], gg = g2[c], bb = be2[c];
  v.x = fmaxf((v.x - m) * rs * gg + bb, 0.f);
  v.y = fmaxf((v.y - m) * rs * gg + bb, 0.f);
  v.z = fmaxf((v.z - m) * rs * gg + bb, 0.f);
  v.w = fmaxf((v.w - m) * rs * gg + bb, 0.f);
  ((float4*)out)[i] = v;
}

// ---------------------------------------------------------------------------
extern "C" void kernel_launch(void* const* d_in, const int* in_sizes, int n_in,
                              void* d_out, int out_size) {
  const float* x   = (const float*)d_in[0];
  const float* nu  = (const float*)d_in[1];
  const float* w1  = (const float*)d_in[2];
  const float* b1  = (const float*)d_in[3];
  const float* g1  = (const float*)d_in[4];
  const float* be1 = (const float*)d_in[5];
  const float* w4  = (const float*)d_in[6];
  const float* b4  = (const float*)d_in[7];
  const float* g2  = (const float*)d_in[8];
  const float* be2 = (const float*)d_in[9];
  float* out = (float*)d_out;

  repack_kernel<<<(KW1 * 128 + 255) / 256, 256>>>(w1);
  conv1_kernel<<<dim3(4, 7, 32), 256>>>(x, nu, b1);
  stats1a_kernel<<<dim3(128, 8), 256>>>();
  reduce1_kernel<<<1, 128>>>();
  bec_kernel<<<EZ / 256, 256>>>(nu, g1, be1);
  dec_kernel<<<dim3(32 * 49, 4), 256>>>(w4, b4, out);
  stats2a_kernel<<<dim3(256, 8), 256>>>(out);
  reduce2_kernel<<<1, 256>>>();
  bn2_kernel<<<out_size / 4 / 256, 256>>>(g2, be2, out);
}

// round 9
// speedup vs baseline: 1.3409x; 1.2195x over previous
#include <cuda_runtime.h>
#include <cstdint>

#define BB 32
#define HH 56
#define HC 128
#define CC 256
#define PIX (HH*HH)          // 3136
#define EZ (BB*HC*PIX)       // 12845056
#define N1 (BB*PIX)          // 100352
#define OHH 112
#define OPIX (OHH*OHH)       // 12544
#define N2 (BB*OPIX)         // 401408

#define KP 264               // padded K (257 -> 264, multiple of 8)
#define NT 25088             // winograd tiles total = 32 b * 784
#define TPB 784              // tiles per batch (28*28)

__device__ __align__(128) float g_z[EZ];            // conv1 out -> BEC output h
__device__ __align__(128) float g_U[16*KP*128];     // transformed weights [p][ic][oc]
__device__ __align__(128) float g_V[16*KP*NT];      // transformed inputs  [p][ic][T]
__device__ __align__(128) float g_M[16*128*NT];     // elementwise products [p][oc][T]
__device__ double g_d1[128*8*2];                    // BN1 partials (sum, sumsq)
__device__ double g_d2[256*8*2];                    // BN2 partials
__device__ float g_m1[HC], g_rs1[HC];
__device__ float g_m2[CC], g_rs2[CC];

// ---------------------------------------------------------------------------
// Kernel A: weight transform  U = G g G^T   (per oc, ic; zero-pad ic>=257)
// ---------------------------------------------------------------------------
__global__ __launch_bounds__(256) void uT_kernel(const float* __restrict__ w1) {
  int i = blockIdx.x * 256 + threadIdx.x;     // over KP*128
  if (i >= KP * 128) return;
  int oc = i & 127, ic = i >> 7;
  float u[4][4];
  if (ic < 257) {
    float g[3][3];
#pragma unroll
    for (int r = 0; r < 3; ++r)
#pragma unroll
      for (int c = 0; c < 3; ++c) g[r][c] = w1[oc * 2313 + ic * 9 + r * 3 + c];
    float t[4][3];
#pragma unroll
    for (int c = 0; c < 3; ++c) {
      t[0][c] = g[0][c];
      t[1][c] = 0.5f * (g[0][c] + g[1][c] + g[2][c]);
      t[2][c] = 0.5f * (g[0][c] - g[1][c] + g[2][c]);
      t[3][c] = g[2][c];
    }
#pragma unroll
    for (int r = 0; r < 4; ++r) {
      u[r][0] = t[r][0];
      u[r][1] = 0.5f * (t[r][0] + t[r][1] + t[r][2]);
      u[r][2] = 0.5f * (t[r][0] - t[r][1] + t[r][2]);
      u[r][3] = t[r][2];
    }
  } else {
#pragma unroll
    for (int r = 0; r < 4; ++r)
#pragma unroll
      for (int c = 0; c < 4; ++c) u[r][c] = 0.f;
  }
#pragma unroll
  for (int p = 0; p < 16; ++p)
    g_U[(p * KP + ic) * 128 + oc] = u[p >> 2][p & 3];
}

// ---------------------------------------------------------------------------
// Kernel B: input transform  V = B^T d B  per 2x2-output tile.
// grid (KP, 32 b); one (b, ic) plane in smem (58x58 zero-padded halo).
// ic==256 -> constant noise plane; ic>=257 -> zeros (K padding).
// ---------------------------------------------------------------------------
__global__ __launch_bounds__(256) void vT_kernel(
    const float* __restrict__ x, const float* __restrict__ nu) {
  __shared__ float sp[58 * 58];
  const int ic = blockIdx.x, b = blockIdx.y, t = threadIdx.x;
  for (int i = t; i < 58 * 58; i += 256) sp[i] = 0.f;
  __syncthreads();
  if (ic < 257) {
    if (ic < 256) {
      const float* xp = x + ((long)b * 256 + ic) * PIX;
      for (int i = t; i < PIX; i += 256) {
        int r = i / 56, c = i - r * 56;
        sp[(r + 1) * 58 + c + 1] = xp[i];
      }
    } else {
      const float nf = nu[0] * 0.5f;
      for (int i = t; i < PIX; i += 256) {
        int r = i / 56, c = i - r * 56;
        sp[(r + 1) * 58 + c + 1] = nf;
      }
    }
  }
  __syncthreads();

  const int base = ic * NT + b * TPB;
  for (int tile = t; tile < TPB; tile += 256) {
    const int ty = tile / 28, tx = tile - ty * 28;
    float d[4][4];
#pragma unroll
    for (int r = 0; r < 4; ++r)
#pragma unroll
      for (int c = 0; c < 4; ++c) d[r][c] = sp[(2 * ty + r) * 58 + 2 * tx + c];
    float td[4][4];
#pragma unroll
    for (int c = 0; c < 4; ++c) {
      td[0][c] = d[0][c] - d[2][c];
      td[1][c] = d[1][c] + d[2][c];
      td[2][c] = d[2][c] - d[1][c];
      td[3][c] = d[1][c] - d[3][c];
    }
    float v[4][4];
#pragma unroll
    for (int r = 0; r < 4; ++r) {
      v[r][0] = td[r][0] - td[r][2];
      v[r][1] = td[r][1] + td[r][2];
      v[r][2] = td[r][2] - td[r][1];
      v[r][3] = td[r][1] - td[r][3];
    }
#pragma unroll
    for (int p = 0; p < 16; ++p)
      g_V[p * (KP * NT) + base + tile] = v[p >> 2][p & 3];
  }
}

// ---------------------------------------------------------------------------
// Kernel C: 16 batched GEMMs  M_p[128 oc][NT] = U_p[128][KP] * V_p[KP][NT].
// Block: 128 oc x 128 T, K chunks of 8, ping-pong smem + register prefetch,
// one sync per chunk.  256 threads: 8 oc x 8 T microtile (64 accs).
// ---------------------------------------------------------------------------
__global__ __launch_bounds__(256) void wgemm_kernel() {
  __shared__ float sU[2][8 * 128];
  __shared__ float sV[2][8 * 128];
  const int t = threadIdx.x;
  const int og = t >> 4, tg = t & 15;
  const int p = blockIdx.y;
  const int Tb = blockIdx.x * 128;
  const int kr = t >> 5, c4 = (t & 31) * 4;

  const float* Ug = g_U + p * (KP * 128);
  const float* Vg = g_V + p * (KP * NT);

  // prologue: stage chunk 0
  {
    float4 u = *(const float4*)&Ug[kr * 128 + c4];
    float4 v = *(const float4*)&Vg[kr * NT + Tb + c4];
    *(float4*)&sU[0][kr * 128 + c4] = u;
    *(float4*)&sV[0][kr * 128 + c4] = v;
  }
  __syncthreads();

  float acc[64];
#pragma unroll
  for (int i = 0; i < 64; ++i) acc[i] = 0.f;

  float4 pu, pv;
  for (int ch = 0; ch < 33; ++ch) {
    const int cur = ch & 1, nxt = cur ^ 1;
    if (ch < 32) {
      const int kn = ch * 8 + 8 + kr;
      pu = *(const float4*)&Ug[kn * 128 + c4];
      pv = *(const float4*)&Vg[kn * NT + Tb + c4];
    }
#pragma unroll
    for (int k = 0; k < 8; ++k) {
      const float4 ua = *(const float4*)&sU[cur][k * 128 + og * 8];
      const float4 ub = *(const float4*)&sU[cur][k * 128 + og * 8 + 4];
      const float4 va = *(const float4*)&sV[cur][k * 128 + tg * 8];
      const float4 vb = *(const float4*)&sV[cur][k * 128 + tg * 8 + 4];
      const float uu[8] = {ua.x, ua.y, ua.z, ua.w, ub.x, ub.y, ub.z, ub.w};
      const float vv[8] = {va.x, va.y, va.z, va.w, vb.x, vb.y, vb.z, vb.w};
#pragma unroll
      for (int j = 0; j < 8; ++j)
#pragma unroll
        for (int i = 0; i < 8; ++i) acc[j * 8 + i] += uu[j] * vv[i];
    }
    if (ch < 32) {
      *(float4*)&sU[nxt][kr * 128 + c4] = pu;
      *(float4*)&sV[nxt][kr * 128 + c4] = pv;
    }
    __syncthreads();
  }

#pragma unroll
  for (int j = 0; j < 8; ++j) {
    float* dst = g_M + (p * 128 + og * 8 + j) * NT + Tb + tg * 8;
    ((float4*)dst)[0] = make_float4(acc[j*8+0], acc[j*8+1], acc[j*8+2], acc[j*8+3]);
    ((float4*)dst)[1] = make_float4(acc[j*8+4], acc[j*8+5], acc[j*8+6], acc[j*8+7]);
  }
}

// ---------------------------------------------------------------------------
// Kernel D: output transform  Y = A^T M A  (+bias) -> g_z
// ---------------------------------------------------------------------------
__global__ __launch_bounds__(256) void oT_kernel(const float* __restrict__ b1) {
  const int i = blockIdx.x * 256 + threadIdx.x;   // (b*128+oc)*784 + tile
  const int tile = i % TPB;
  const int boc = i / TPB;
  const int oc = boc & 127, b = boc >> 7;
  const int Ti = b * TPB + tile;

  float m[4][4];
#pragma unroll
  for (int p = 0; p < 16; ++p)
    m[p >> 2][p & 3] = g_M[(p * 128 + oc) * NT + Ti];

  float s[2][4];
#pragma unroll
  for (int c = 0; c < 4; ++c) {
    s[0][c] = m[0][c] + m[1][c] + m[2][c];
    s[1][c] = m[1][c] - m[2][c] - m[3][c];
  }
  const float bb = b1[oc];
  const float y00 = s[0][0] + s[0][1] + s[0][2] + bb;
  const float y01 = s[0][1] - s[0][2] - s[0][3] + bb;
  const float y10 = s[1][0] + s[1][1] + s[1][2] + bb;
  const float y11 = s[1][1] - s[1][2] - s[1][3] + bb;

  const int ty = tile / 28, tx = tile - ty * 28;
  float* dst = g_z + ((b * 128 + oc) * HH + 2 * ty) * HH + 2 * tx;
  *(float2*)dst = make_float2(y00, y01);
  *(float2*)(dst + HH) = make_float2(y10, y11);
}

// ---------------------------------------------------------------------------
// Kernel 2a: BN1 partial stats — grid (128 ch, 8 slices), 4 batches/slice
// ---------------------------------------------------------------------------
__global__ __launch_bounds__(256) void stats1a_kernel() {
  const int c = blockIdx.x, sl = blockIdx.y, t = threadIdx.x;
  double s = 0.0, q = 0.0;
  for (int bb = sl * 4; bb < sl * 4 + 4; ++bb) {
    const float4* p = (const float4*)(g_z + (bb * 128 + c) * PIX);
    for (int i = t; i < PIX / 4; i += 256) {
      float4 v = p[i];
      s += (double)v.x + v.y + v.z + v.w;
      q += (double)v.x * v.x + (double)v.y * v.y +
           (double)v.z * v.z + (double)v.w * v.w;
    }
  }
  __shared__ double ss[256], sq[256];
  ss[t] = s; sq[t] = q;
  __syncthreads();
  for (int o = 128; o > 0; o >>= 1) {
    if (t < o) { ss[t] += ss[t + o]; sq[t] += sq[t + o]; }
    __syncthreads();
  }
  if (t == 0) {
    g_d1[(c * 8 + sl) * 2 + 0] = ss[0];
    g_d1[(c * 8 + sl) * 2 + 1] = sq[0];
  }
}

__global__ __launch_bounds__(128) void reduce1_kernel() {
  const int c = threadIdx.x;
  double s = 0.0, q = 0.0;
#pragma unroll
  for (int sl = 0; sl < 8; ++sl) {
    s += g_d1[(c * 8 + sl) * 2 + 0];
    q += g_d1[(c * 8 + sl) * 2 + 1];
  }
  double m   = s / N1;
  double var = q / N1 - m * m;
  g_m1[c]  = (float)m;
  g_rs1[c] = rsqrtf((float)var + 1e-5f);
}

// ---------------------------------------------------------------------------
// Threefry2x32, key (0,42), partitionable draw: x0=0, x1=j, out = o0^o1.
// ---------------------------------------------------------------------------
__device__ __forceinline__ unsigned tf_xor(unsigned j) {
  const unsigned ks0 = 0u, ks1 = 42u, ks2 = 0x1BD11BDAu ^ 42u;
  unsigned x0 = 0u + ks0;
  unsigned x1 = j  + ks1;
#define TFRND(r) { x0 += x1; x1 = __funnelshift_l(x1, x1, r); x1 ^= x0; }
  TFRND(13) TFRND(15) TFRND(26) TFRND(6)
  x0 += ks1; x1 += ks2 + 1u;
  TFRND(17) TFRND(29) TFRND(16) TFRND(24)
  x0 += ks2; x1 += ks0 + 2u;
  TFRND(13) TFRND(15) TFRND(26) TFRND(6)
  x0 += ks0; x1 += ks1 + 3u;
  TFRND(17) TFRND(29) TFRND(16) TFRND(24)
  x0 += ks1; x1 += ks2 + 4u;
  TFRND(13) TFRND(15) TFRND(26) TFRND(6)
  x0 += ks2; x1 += ks0 + 5u;
#undef TFRND
  return x0 ^ x1;
}

// ---------------------------------------------------------------------------
// Kernel 3: BN1 apply + sigmoid + quantize + BEC (in place on g_z)
// ---------------------------------------------------------------------------
__global__ __launch_bounds__(256) void bec_kernel(
    const float* __restrict__ nu, const float* __restrict__ g1,
    const float* __restrict__ be1) {
  const int e = blockIdx.x * 256 + threadIdx.x;
  const int c = (e / PIX) & 127;
  const float z = g_z[e];
  float tt = (z - g_m1[c]) * g_rs1[c] * g1[c] + be1[c];
  float s  = 0.5f * tanhf(0.5f * tt) + 0.5f;
  float r  = rintf(s * 256.0f);
  if (r >= 256.0f) r -= 256.0f;
  const unsigned xb = (unsigned)r;

  const float q = 1.0f - nu[0] * 0.5f;
  unsigned mask = 0u;
#pragma unroll
  for (int k = 0; k < 8; ++k) {
    unsigned bits = tf_xor((unsigned)(k * EZ + e));
    float u = __uint_as_float((bits >> 9) | 0x3f800000u) - 1.0f;
    if (u < q) mask |= (1u << k);
  }
  float outv = ((float)(xb & mask) + (255.0f - (float)mask) / 2.0f) / 255.0f;
  g_z[e] = outv;
}

// ---------------------------------------------------------------------------
// Kernel 4: ConvTranspose2d(k2,s2) as 4-tap GEMM (FFMA, ~97% of roofline).
// ---------------------------------------------------------------------------
__global__ __launch_bounds__(256) void dec_kernel(
    const float* __restrict__ w4, const float* __restrict__ b4,
    float* __restrict__ out) {
  __shared__ float4 ws4[16 * 64];
  __shared__ float4 hs4[16 * 16];
  const int t = threadIdx.x;
  const int bp = blockIdx.x;
  const int b = bp / 49;
  const int pixb = (bp % 49) * 64;
  const int cb = blockIdx.y * 64;
  const int pgrp = t & 7;
  const int cgrp = t >> 3;

  float acc[64];
#pragma unroll
  for (int i = 0; i < 64; ++i) acc[i] = 0.f;

  const float4* w44 = (const float4*)w4;
  const float4* gz4 = (const float4*)g_z;

  for (int hc0 = 0; hc0 < 128; hc0 += 16) {
    __syncthreads();
#pragma unroll
    for (int i = 0; i < 4; ++i) {
      int idx = t + i * 256;
      int hh = idx >> 6, cl = idx & 63;
      ws4[idx] = w44[(hc0 + hh) * 256 + cb + cl];
    }
    {
      int hh = t >> 4, p4 = t & 15;
      hs4[t] = gz4[((b * 128 + hc0 + hh) * PIX + pixb) / 4 + p4];
    }
    __syncthreads();
#pragma unroll
    for (int hh = 0; hh < 16; ++hh) {
      const float4 h0 = hs4[hh * 16 + pgrp * 2];
      const float4 h1 = hs4[hh * 16 + pgrp * 2 + 1];
      const float4 wa = ws4[hh * 64 + cgrp * 2];
      const float4 wb = ws4[hh * 64 + cgrp * 2 + 1];
      const float hv[8] = {h0.x, h0.y, h0.z, h0.w, h1.x, h1.y, h1.z, h1.w};
#pragma unroll
      for (int pp = 0; pp < 8; ++pp) {
        acc[pp * 4 + 0] += hv[pp] * wa.x;
        acc[pp * 4 + 1] += hv[pp] * wa.y;
        acc[pp * 4 + 2] += hv[pp] * wa.z;
        acc[pp * 4 + 3] += hv[pp] * wa.w;
        acc[32 + pp * 4 + 0] += hv[pp] * wb.x;
        acc[32 + pp * 4 + 1] += hv[pp] * wb.y;
        acc[32 + pp * 4 + 2] += hv[pp] * wb.z;
        acc[32 + pp * 4 + 3] += hv[pp] * wb.w;
      }
    }
  }

#pragma unroll
  for (int cc = 0; cc < 2; ++cc) {
    const int c = cb + cgrp * 2 + cc;
    const float bb = b4[c];
#pragma unroll
    for (int pp = 0; pp < 8; ++pp) {
      const int pix = pixb + pgrp * 8 + pp;
      const int ih = pix / HH, iw = pix % HH;
      float* dst = out + ((b * 256 + c) * OHH + 2 * ih) * OHH + 2 * iw;
      float2 top = {acc[cc * 32 + pp * 4 + 0] + bb, acc[cc * 32 + pp * 4 + 1] + bb};
      float2 bot = {acc[cc * 32 + pp * 4 + 2] + bb, acc[cc * 32 + pp * 4 + 3] + bb};
      *(float2*)dst = top;
      *(float2*)(dst + OHH) = bot;
    }
  }
}

// ---------------------------------------------------------------------------
// Kernel 5a: BN2 partial stats — grid (256 ch, 8 slices), 4 batches/slice
// ---------------------------------------------------------------------------
__global__ __launch_bounds__(256) void stats2a_kernel(const float* __restrict__ out) {
  const int c = blockIdx.x, sl = blockIdx.y, t = threadIdx.x;
  double s = 0.0, q = 0.0;
  for (int bb = sl * 4; bb < sl * 4 + 4; ++bb) {
    const float4* p = (const float4*)(out + (bb * 256 + c) * OPIX);
    for (int i = t; i < OPIX / 4; i += 256) {
      float4 v = p[i];
      s += (double)v.x + v.y + v.z + v.w;
      q += (double)v.x * v.x + (double)v.y * v.y +
           (double)v.z * v.z + (double)v.w * v.w;
    }
  }
  __shared__ double ss[256], sq[256];
  ss[t] = s; sq[t] = q;
  __syncthreads();
  for (int o = 128; o > 0; o >>= 1) {
    if (t < o) { ss[t] += ss[t + o]; sq[t] += sq[t + o]; }
    __syncthreads();
  }
  if (t == 0) {
    g_d2[(c * 8 + sl) * 2 + 0] = ss[0];
    g_d2[(c * 8 + sl) * 2 + 1] = sq[0];
  }
}

__global__ __launch_bounds__(256) void reduce2_kernel() {
  const int c = threadIdx.x;
  double s = 0.0, q = 0.0;
#pragma unroll
  for (int sl = 0; sl < 8; ++sl) {
    s += g_d2[(c * 8 + sl) * 2 + 0];
    q += g_d2[(c * 8 + sl) * 2 + 1];
  }
  double m   = s / N2;
  double var = q / N2 - m * m;
  g_m2[c]  = (float)m;
  g_rs2[c] = rsqrtf((float)var + 1e-5f);
}

// ---------------------------------------------------------------------------
// Kernel 6: BN2 apply + relu, in place on d_out
// ---------------------------------------------------------------------------
__global__ __launch_bounds__(256) void bn2_kernel(
    const float* __restrict__ g2, const float* __restrict__ be2,
    float* __restrict__ out) {
  const int i = blockIdx.x * 256 + threadIdx.x;
  const int c = (i / (OPIX / 4)) & 255;
  float4 v = ((float4*)out)[i];
  const float m = g_m2[c], rs = g_rs2[c], gg = g2[c], bb = be2[c];
  v.x = fmaxf((v.x - m) * rs * gg + bb, 0.f);
  v.y = fmaxf((v.y - m) * rs * gg + bb, 0.f);
  v.z = fmaxf((v.z - m) * rs * gg + bb, 0.f);
  v.w = fmaxf((v.w - m) * rs * gg + bb, 0.f);
  ((float4*)out)[i] = v;
}

// ---------------------------------------------------------------------------
extern "C" void kernel_launch(void* const* d_in, const int* in_sizes, int n_in,
                              void* d_out, int out_size) {
  const float* x   = (const float*)d_in[0];
  const float* nu  = (const float*)d_in[1];
  const float* w1  = (const float*)d_in[2];
  const float* b1  = (const float*)d_in[3];
  const float* g1  = (const float*)d_in[4];
  const float* be1 = (const float*)d_in[5];
  const float* w4  = (const float*)d_in[6];
  const float* b4  = (const float*)d_in[7];
  const float* g2  = (const float*)d_in[8];
  const float* be2 = (const float*)d_in[9];
  float* out = (float*)d_out;

  uT_kernel<<<(KP * 128 + 255) / 256, 256>>>(w1);
  vT_kernel<<<dim3(KP, 32), 256>>>(x, nu);
  wgemm_kernel<<<dim3(NT / 128, 16), 256>>>();
  oT_kernel<<<(BB * 128 * TPB) / 256, 256>>>(b1);
  stats1a_kernel<<<dim3(128, 8), 256>>>();
  reduce1_kernel<<<1, 128>>>();
  bec_kernel<<<EZ / 256, 256>>>(nu, g1, be1);
  dec_kernel<<<dim3(32 * 49, 4), 256>>>(w4, b4, out);
  stats2a_kernel<<<dim3(256, 8), 256>>>(out);
  reduce2_kernel<<<1, 256>>>();
  bn2_kernel<<<out_size / 4 / 256, 256>>>(g2, be2, out);
}

// round 10
// speedup vs baseline: 1.4797x; 1.1035x over previous
#include <cuda_runtime.h>
#include <cstdint>

#define BB 32
#define HH 56
#define HC 128
#define CC 256
#define PIX (HH*HH)          // 3136
#define EZ (BB*HC*PIX)       // 12845056
#define N1 (BB*PIX)          // 100352
#define OHH 112
#define OPIX (OHH*OHH)       // 12544
#define N2 (BB*OPIX)         // 401408

#define KP 264               // padded K (257 -> 264)
#define TPB 196              // 14x14 tiles per batch (F(4x4): 56/4)
#define NT (BB*TPB)          // 6272 tiles total

__device__ __align__(128) float g_z[EZ];            // conv1 out -> BEC output h
__device__ __align__(128) float g_U[36*KP*128];     // transformed weights [p][ic][oc]
__device__ __align__(128) float g_V[36*KP*NT];      // transformed inputs  [p][ic][T]
__device__ __align__(128) float g_M[36*128*NT];     // products [p][oc][T]
__device__ double g_d1[128*8*2];                    // BN1 partials
__device__ double g_d2[256*8*2];                    // BN2 partials
__device__ float g_m1[HC], g_rs1[HC];
__device__ float g_m2[CC], g_rs2[CC];

// ---------------------------------------------------------------------------
// Kernel A: weight transform  U = G g G^T  for F(4x4,3x3)
// G = [1/4 0 0; -1/6 -1/6 -1/6; -1/6 1/6 -1/6; 1/24 1/12 1/6; 1/24 -1/12 1/6; 0 0 1]
// ---------------------------------------------------------------------------
__global__ __launch_bounds__(256) void uT_kernel(const float* __restrict__ w1) {
  int i = blockIdx.x * 256 + threadIdx.x;
  if (i >= KP * 128) return;
  int oc = i & 127, ic = i >> 7;
  float u[6][6];
  if (ic < 257) {
    float g[3][3];
#pragma unroll
    for (int r = 0; r < 3; ++r)
#pragma unroll
      for (int c = 0; c < 3; ++c) g[r][c] = w1[oc * 2313 + ic * 9 + r * 3 + c];
    float t[6][3];
#pragma unroll
    for (int c = 0; c < 3; ++c) {
      t[0][c] = 0.25f * g[0][c];
      t[1][c] = (-1.f/6.f) * (g[0][c] + g[1][c] + g[2][c]);
      t[2][c] = (1.f/6.f) * (-g[0][c] + g[1][c] - g[2][c]);
      t[3][c] = (1.f/24.f) * g[0][c] + (1.f/12.f) * g[1][c] + (1.f/6.f) * g[2][c];
      t[4][c] = (1.f/24.f) * g[0][c] - (1.f/12.f) * g[1][c] + (1.f/6.f) * g[2][c];
      t[5][c] = g[2][c];
    }
#pragma unroll
    for (int r = 0; r < 6; ++r) {
      u[r][0] = 0.25f * t[r][0];
      u[r][1] = (-1.f/6.f) * (t[r][0] + t[r][1] + t[r][2]);
      u[r][2] = (1.f/6.f) * (-t[r][0] + t[r][1] - t[r][2]);
      u[r][3] = (1.f/24.f) * t[r][0] + (1.f/12.f) * t[r][1] + (1.f/6.f) * t[r][2];
      u[r][4] = (1.f/24.f) * t[r][0] - (1.f/12.f) * t[r][1] + (1.f/6.f) * t[r][2];
      u[r][5] = t[r][2];
    }
  } else {
#pragma unroll
    for (int r = 0; r < 6; ++r)
#pragma unroll
      for (int c = 0; c < 6; ++c) u[r][c] = 0.f;
  }
#pragma unroll
  for (int p = 0; p < 36; ++p)
    g_U[(p * KP + ic) * 128 + oc] = u[p / 6][p % 6];
}

// ---------------------------------------------------------------------------
// Kernel B: input transform  V = B^T d B  per 4x4-output tile (6x6 input).
// B^T rows: [4 0 -5 0 1 0; 0 -4 -4 1 1 0; 0 4 -4 -1 1 0; 0 -2 -1 2 1 0;
//            0 2 -1 -2 1 0; 0 4 0 -5 0 1]
// grid (KP, 32 b); one (b, ic) plane in smem (58x58 padded halo).
// ---------------------------------------------------------------------------
__global__ __launch_bounds__(256) void vT_kernel(
    const float* __restrict__ x, const float* __restrict__ nu) {
  __shared__ float sp[58 * 58];
  const int ic = blockIdx.x, b = blockIdx.y, t = threadIdx.x;
  for (int i = t; i < 58 * 58; i += 256) sp[i] = 0.f;
  __syncthreads();
  if (ic < 257) {
    if (ic < 256) {
      const float* xp = x + ((long)b * 256 + ic) * PIX;
      for (int i = t; i < PIX; i += 256) {
        int r = i / 56, c = i - r * 56;
        sp[(r + 1) * 58 + c + 1] = xp[i];
      }
    } else {
      const float nf = nu[0] * 0.5f;
      for (int i = t; i < PIX; i += 256) {
        int r = i / 56, c = i - r * 56;
        sp[(r + 1) * 58 + c + 1] = nf;
      }
    }
  }
  __syncthreads();

  const int base = ic * NT + b * TPB;
  for (int tile = t; tile < TPB; tile += 256) {
    const int ty = tile / 14, tx = tile - ty * 14;
    float d[6][6];
#pragma unroll
    for (int r = 0; r < 6; ++r)
#pragma unroll
      for (int c = 0; c < 6; ++c) d[r][c] = sp[(4 * ty + r) * 58 + 4 * tx + c];
    float td[6][6];
#pragma unroll
    for (int c = 0; c < 6; ++c) {
      td[0][c] = 4.f * d[0][c] - 5.f * d[2][c] + d[4][c];
      td[1][c] = -4.f * d[1][c] - 4.f * d[2][c] + d[3][c] + d[4][c];
      td[2][c] = 4.f * d[1][c] - 4.f * d[2][c] - d[3][c] + d[4][c];
      td[3][c] = -2.f * d[1][c] - d[2][c] + 2.f * d[3][c] + d[4][c];
      td[4][c] = 2.f * d[1][c] - d[2][c] - 2.f * d[3][c] + d[4][c];
      td[5][c] = 4.f * d[1][c] - 5.f * d[3][c] + d[5][c];
    }
    float v[6][6];
#pragma unroll
    for (int r = 0; r < 6; ++r) {
      v[r][0] = 4.f * td[r][0] - 5.f * td[r][2] + td[r][4];
      v[r][1] = -4.f * td[r][1] - 4.f * td[r][2] + td[r][3] + td[r][4];
      v[r][2] = 4.f * td[r][1] - 4.f * td[r][2] - td[r][3] + td[r][4];
      v[r][3] = -2.f * td[r][1] - td[r][2] + 2.f * td[r][3] + td[r][4];
      v[r][4] = 2.f * td[r][1] - td[r][2] - 2.f * td[r][3] + td[r][4];
      v[r][5] = 4.f * td[r][1] - 5.f * td[r][3] + td[r][5];
    }
#pragma unroll
    for (int p = 0; p < 36; ++p)
      g_V[p * (KP * NT) + base + tile] = v[p / 6][p % 6];
  }
}

// ---------------------------------------------------------------------------
// Kernel C: 36 batched GEMMs  M_p[128 oc][NT] = U_p[128][KP] * V_p[KP][NT].
// Block: 128 oc x 128 T, K chunks of 8, ping-pong smem + register prefetch.
// 256 threads: 8 oc x 8 T microtile.  grid (NT/128 = 49, 36).
// ---------------------------------------------------------------------------
__global__ __launch_bounds__(256) void wgemm_kernel() {
  __shared__ float sU[2][8 * 128];
  __shared__ float sV[2][8 * 128];
  const int t = threadIdx.x;
  const int og = t >> 4, tg = t & 15;
  const int p = blockIdx.y;
  const int Tb = blockIdx.x * 128;
  const int kr = t >> 5, c4 = (t & 31) * 4;

  const float* Ug = g_U + p * (KP * 128);
  const float* Vg = g_V + (long)p * (KP * NT);

  {
    float4 u = *(const float4*)&Ug[kr * 128 + c4];
    float4 v = *(const float4*)&Vg[kr * NT + Tb + c4];
    *(float4*)&sU[0][kr * 128 + c4] = u;
    *(float4*)&sV[0][kr * 128 + c4] = v;
  }
  __syncthreads();

  float acc[64];
#pragma unroll
  for (int i = 0; i < 64; ++i) acc[i] = 0.f;

  float4 pu, pv;
  for (int ch = 0; ch < 33; ++ch) {
    const int cur = ch & 1, nxt = cur ^ 1;
    if (ch < 32) {
      const int kn = ch * 8 + 8 + kr;
      pu = *(const float4*)&Ug[kn * 128 + c4];
      pv = *(const float4*)&Vg[kn * NT + Tb + c4];
    }
#pragma unroll
    for (int k = 0; k < 8; ++k) {
      const float4 ua = *(const float4*)&sU[cur][k * 128 + og * 8];
      const float4 ub = *(const float4*)&sU[cur][k * 128 + og * 8 + 4];
      const float4 va = *(const float4*)&sV[cur][k * 128 + tg * 8];
      const float4 vb = *(const float4*)&sV[cur][k * 128 + tg * 8 + 4];
      const float uu[8] = {ua.x, ua.y, ua.z, ua.w, ub.x, ub.y, ub.z, ub.w};
      const float vv[8] = {va.x, va.y, va.z, va.w, vb.x, vb.y, vb.z, vb.w};
#pragma unroll
      for (int j = 0; j < 8; ++j)
#pragma unroll
        for (int i = 0; i < 8; ++i) acc[j * 8 + i] += uu[j] * vv[i];
    }
    if (ch < 32) {
      *(float4*)&sU[nxt][kr * 128 + c4] = pu;
      *(float4*)&sV[nxt][kr * 128 + c4] = pv;
    }
    __syncthreads();
  }

#pragma unroll
  for (int j = 0; j < 8; ++j) {
    float* dst = g_M + ((long)p * 128 + og * 8 + j) * NT + Tb + tg * 8;
    ((float4*)dst)[0] = make_float4(acc[j*8+0], acc[j*8+1], acc[j*8+2], acc[j*8+3]);
    ((float4*)dst)[1] = make_float4(acc[j*8+4], acc[j*8+5], acc[j*8+6], acc[j*8+7]);
  }
}

// ---------------------------------------------------------------------------
// Kernel D: output transform  Y = A^T M A  (+bias) -> g_z   (4x4 outputs)
// A^T rows: [1 1 1 1 1 0; 0 1 -1 2 -2 0; 0 1 1 4 4 0; 0 1 -1 8 -8 1]
// ---------------------------------------------------------------------------
__global__ __launch_bounds__(256) void oT_kernel(const float* __restrict__ b1) {
  const int i = blockIdx.x * 256 + threadIdx.x;   // (b*128+oc)*196 + tile
  const int tile = i % TPB;
  const int boc = i / TPB;
  const int oc = boc & 127, b = boc >> 7;
  const int Ti = b * TPB + tile;

  float m[6][6];
#pragma unroll
  for (int p = 0; p < 36; ++p)
    m[p / 6][p % 6] = g_M[((long)p * 128 + oc) * NT + Ti];

  float s[4][6];
#pragma unroll
  for (int c = 0; c < 6; ++c) {
    s[0][c] = m[0][c] + m[1][c] + m[2][c] + m[3][c] + m[4][c];
    s[1][c] = m[1][c] - m[2][c] + 2.f * m[3][c] - 2.f * m[4][c];
    s[2][c] = m[1][c] + m[2][c] + 4.f * m[3][c] + 4.f * m[4][c];
    s[3][c] = m[1][c] - m[2][c] + 8.f * m[3][c] - 8.f * m[4][c] + m[5][c];
  }
  const float bb = b1[oc];
  const int ty = tile / 14, tx = tile - ty * 14;
  float* dst = g_z + ((b * 128 + oc) * HH + 4 * ty) * HH + 4 * tx;
#pragma unroll
  for (int r = 0; r < 4; ++r) {
    float y0 = s[r][0] + s[r][1] + s[r][2] + s[r][3] + s[r][4] + bb;
    float y1 = s[r][1] - s[r][2] + 2.f * s[r][3] - 2.f * s[r][4] + bb;
    float y2 = s[r][1] + s[r][2] + 4.f * s[r][3] + 4.f * s[r][4] + bb;
    float y3 = s[r][1] - s[r][2] + 8.f * s[r][3] - 8.f * s[r][4] + s[r][5] + bb;
    *(float4*)(dst + r * HH) = make_float4(y0, y1, y2, y3);
  }
}

// ---------------------------------------------------------------------------
// Kernel 2a: BN1 partial stats — grid (128 ch, 8 slices), 4 batches/slice
// ---------------------------------------------------------------------------
__global__ __launch_bounds__(256) void stats1a_kernel() {
  const int c = blockIdx.x, sl = blockIdx.y, t = threadIdx.x;
  double s = 0.0, q = 0.0;
  for (int bb = sl * 4; bb < sl * 4 + 4; ++bb) {
    const float4* p = (const float4*)(g_z + (bb * 128 + c) * PIX);
    for (int i = t; i < PIX / 4; i += 256) {
      float4 v = p[i];
      s += (double)v.x + v.y + v.z + v.w;
      q += (double)v.x * v.x + (double)v.y * v.y +
           (double)v.z * v.z + (double)v.w * v.w;
    }
  }
  __shared__ double ss[256], sq[256];
  ss[t] = s; sq[t] = q;
  __syncthreads();
  for (int o = 128; o > 0; o >>= 1) {
    if (t < o) { ss[t] += ss[t + o]; sq[t] += sq[t + o]; }
    __syncthreads();
  }
  if (t == 0) {
    g_d1[(c * 8 + sl) * 2 + 0] = ss[0];
    g_d1[(c * 8 + sl) * 2 + 1] = sq[0];
  }
}

__global__ __launch_bounds__(128) void reduce1_kernel() {
  const int c = threadIdx.x;
  double s = 0.0, q = 0.0;
#pragma unroll
  for (int sl = 0; sl < 8; ++sl) {
    s += g_d1[(c * 8 + sl) * 2 + 0];
    q += g_d1[(c * 8 + sl) * 2 + 1];
  }
  double m   = s / N1;
  double var = q / N1 - m * m;
  g_m1[c]  = (float)m;
  g_rs1[c] = rsqrtf((float)var + 1e-5f);
}

// ---------------------------------------------------------------------------
// Threefry2x32, key (0,42), partitionable draw: x0=0, x1=j, out = o0^o1.
// ---------------------------------------------------------------------------
__device__ __forceinline__ unsigned tf_xor(unsigned j) {
  const unsigned ks0 = 0u, ks1 = 42u, ks2 = 0x1BD11BDAu ^ 42u;
  unsigned x0 = 0u + ks0;
  unsigned x1 = j  + ks1;
#define TFRND(r) { x0 += x1; x1 = __funnelshift_l(x1, x1, r); x1 ^= x0; }
  TFRND(13) TFRND(15) TFRND(26) TFRND(6)
  x0 += ks1; x1 += ks2 + 1u;
  TFRND(17) TFRND(29) TFRND(16) TFRND(24)
  x0 += ks2; x1 += ks0 + 2u;
  TFRND(13) TFRND(15) TFRND(26) TFRND(6)
  x0 += ks0; x1 += ks1 + 3u;
  TFRND(17) TFRND(29) TFRND(16) TFRND(24)
  x0 += ks1; x1 += ks2 + 4u;
  TFRND(13) TFRND(15) TFRND(26) TFRND(6)
  x0 += ks2; x1 += ks0 + 5u;
#undef TFRND
  return x0 ^ x1;
}

// ---------------------------------------------------------------------------
// Kernel 3: BN1 apply + sigmoid + quantize + BEC (in place on g_z)
// ---------------------------------------------------------------------------
__global__ __launch_bounds__(256) void bec_kernel(
    const float* __restrict__ nu, const float* __restrict__ g1,
    const float* __restrict__ be1) {
  const int e = blockIdx.x * 256 + threadIdx.x;
  const int c = (e / PIX) & 127;
  const float z = g_z[e];
  float tt = (z - g_m1[c]) * g_rs1[c] * g1[c] + be1[c];
  float s  = 0.5f * tanhf(0.5f * tt) + 0.5f;
  float r  = rintf(s * 256.0f);
  if (r >= 256.0f) r -= 256.0f;
  const unsigned xb = (unsigned)r;

  const float q = 1.0f - nu[0] * 0.5f;
  unsigned mask = 0u;
#pragma unroll
  for (int k = 0; k < 8; ++k) {
    unsigned bits = tf_xor((unsigned)(k * EZ + e));
    float u = __uint_as_float((bits >> 9) | 0x3f800000u) - 1.0f;
    if (u < q) mask |= (1u << k);
  }
  float outv = ((float)(xb & mask) + (255.0f - (float)mask) / 2.0f) / 255.0f;
  g_z[e] = outv;
}

// ---------------------------------------------------------------------------
// Kernel 4: ConvTranspose2d(k2,s2) as 4-tap GEMM (FFMA, ~97% of roofline).
// ---------------------------------------------------------------------------
__global__ __launch_bounds__(256) void dec_kernel(
    const float* __restrict__ w4, const float* __restrict__ b4,
    float* __restrict__ out) {
  __shared__ float4 ws4[16 * 64];
  __shared__ float4 hs4[16 * 16];
  const int t = threadIdx.x;
  const int bp = blockIdx.x;
  const int b = bp / 49;
  const int pixb = (bp % 49) * 64;
  const int cb = blockIdx.y * 64;
  const int pgrp = t & 7;
  const int cgrp = t >> 3;

  float acc[64];
#pragma unroll
  for (int i = 0; i < 64; ++i) acc[i] = 0.f;

  const float4* w44 = (const float4*)w4;
  const float4* gz4 = (const float4*)g_z;

  for (int hc0 = 0; hc0 < 128; hc0 += 16) {
    __syncthreads();
#pragma unroll
    for (int i = 0; i < 4; ++i) {
      int idx = t + i * 256;
      int hh = idx >> 6, cl = idx & 63;
      ws4[idx] = w44[(hc0 + hh) * 256 + cb + cl];
    }
    {
      int hh = t >> 4, p4 = t & 15;
      hs4[t] = gz4[((b * 128 + hc0 + hh) * PIX + pixb) / 4 + p4];
    }
    __syncthreads();
#pragma unroll
    for (int hh = 0; hh < 16; ++hh) {
      const float4 h0 = hs4[hh * 16 + pgrp * 2];
      const float4 h1 = hs4[hh * 16 + pgrp * 2 + 1];
      const float4 wa = ws4[hh * 64 + cgrp * 2];
      const float4 wb = ws4[hh * 64 + cgrp * 2 + 1];
      const float hv[8] = {h0.x, h0.y, h0.z, h0.w, h1.x, h1.y, h1.z, h1.w};
#pragma unroll
      for (int pp = 0; pp < 8; ++pp) {
        acc[pp * 4 + 0] += hv[pp] * wa.x;
        acc[pp * 4 + 1] += hv[pp] * wa.y;
        acc[pp * 4 + 2] += hv[pp] * wa.z;
        acc[pp * 4 + 3] += hv[pp] * wa.w;
        acc[32 + pp * 4 + 0] += hv[pp] * wb.x;
        acc[32 + pp * 4 + 1] += hv[pp] * wb.y;
        acc[32 + pp * 4 + 2] += hv[pp] * wb.z;
        acc[32 + pp * 4 + 3] += hv[pp] * wb.w;
      }
    }
  }

#pragma unroll
  for (int cc = 0; cc < 2; ++cc) {
    const int c = cb + cgrp * 2 + cc;
    const float bb = b4[c];
#pragma unroll
    for (int pp = 0; pp < 8; ++pp) {
      const int pix = pixb + pgrp * 8 + pp;
      const int ih = pix / HH, iw = pix % HH;
      float* dst = out + ((b * 256 + c) * OHH + 2 * ih) * OHH + 2 * iw;
      float2 top = {acc[cc * 32 + pp * 4 + 0] + bb, acc[cc * 32 + pp * 4 + 1] + bb};
      float2 bot = {acc[cc * 32 + pp * 4 + 2] + bb, acc[cc * 32 + pp * 4 + 3] + bb};
      *(float2*)dst = top;
      *(float2*)(dst + OHH) = bot;
    }
  }
}

// ---------------------------------------------------------------------------
// Kernel 5a: BN2 partial stats — grid (256 ch, 8 slices), 4 batches/slice
// ---------------------------------------------------------------------------
__global__ __launch_bounds__(256) void stats2a_kernel(const float* __restrict__ out) {
  const int c = blockIdx.x, sl = blockIdx.y, t = threadIdx.x;
  double s = 0.0, q = 0.0;
  for (int bb = sl * 4; bb < sl * 4 + 4; ++bb) {
    const float4* p = (const float4*)(out + (bb * 256 + c) * OPIX);
    for (int i = t; i < OPIX / 4; i += 256) {
      float4 v = p[i];
      s += (double)v.x + v.y + v.z + v.w;
      q += (double)v.x * v.x + (double)v.y * v.y +
           (double)v.z * v.z + (double)v.w * v.w;
    }
  }
  __shared__ double ss[256], sq[256];
  ss[t] = s; sq[t] = q;
  __syncthreads();
  for (int o = 128; o > 0; o >>= 1) {
    if (t < o) { ss[t] += ss[t + o]; sq[t] += sq[t + o]; }
    __syncthreads();
  }
  if (t == 0) {
    g_d2[(c * 8 + sl) * 2 + 0] = ss[0];
    g_d2[(c * 8 + sl) * 2 + 1] = sq[0];
  }
}

__global__ __launch_bounds__(256) void reduce2_kernel() {
  const int c = threadIdx.x;
  double s = 0.0, q = 0.0;
#pragma unroll
  for (int sl = 0; sl < 8; ++sl) {
    s += g_d2[(c * 8 + sl) * 2 + 0];
    q += g_d2[(c * 8 + sl) * 2 + 1];
  }
  double m   = s / N2;
  double var = q / N2 - m * m;
  g_m2[c]  = (float)m;
  g_rs2[c] = rsqrtf((float)var + 1e-5f);
}

// ---------------------------------------------------------------------------
// Kernel 6: BN2 apply + relu, in place on d_out
// ---------------------------------------------------------------------------
__global__ __launch_bounds__(256) void bn2_kernel(
    const float* __restrict__ g2, const float* __restrict__ be2,
    float* __restrict__ out) {
  const int i = blockIdx.x * 256 + threadIdx.x;
  const int c = (i / (OPIX / 4)) & 255;
  float4 v = ((float4*)out)[i];
  const float m = g_m2[c], rs = g_rs2[c], gg = g2[c], bb = be2[c];
  v.x = fmaxf((v.x - m) * rs * gg + bb, 0.f);
  v.y = fmaxf((v.y - m) * rs * gg + bb, 0.f);
  v.z = fmaxf((v.z - m) * rs * gg + bb, 0.f);
  v.w = fmaxf((v.w - m) * rs * gg + bb, 0.f);
  ((float4*)out)[i] = v;
}

// ---------------------------------------------------------------------------
extern "C" void kernel_launch(void* const* d_in, const int* in_sizes, int n_in,
                              void* d_out, int out_size) {
  const float* x   = (const float*)d_in[0];
  const float* nu  = (const float*)d_in[1];
  const float* w1  = (const float*)d_in[2];
  const float* b1  = (const float*)d_in[3];
  const float* g1  = (const float*)d_in[4];
  const float* be1 = (const float*)d_in[5];
  const float* w4  = (const float*)d_in[6];
  const float* b4  = (const float*)d_in[7];
  const float* g2  = (const float*)d_in[8];
  const float* be2 = (const float*)d_in[9];
  float* out = (float*)d_out;

  uT_kernel<<<(KP * 128 + 255) / 256, 256>>>(w1);
  vT_kernel<<<dim3(KP, 32), 256>>>(x, nu);
  wgemm_kernel<<<dim3(NT / 128, 36), 256>>>();
  oT_kernel<<<(BB * 128 * TPB) / 256, 256>>>(b1);
  stats1a_kernel<<<dim3(128, 8), 256>>>();
  reduce1_kernel<<<1, 128>>>();
  bec_kernel<<<EZ / 256, 256>>>(nu, g1, be1);
  dec_kernel<<<dim3(32 * 49, 4), 256>>>(w4, b4, out);
  stats2a_kernel<<<dim3(256, 8), 256>>>(out);
  reduce2_kernel<<<1, 256>>>();
  bn2_kernel<<<out_size / 4 / 256, 256>>>(g2, be2, out);
}

// round 11
// speedup vs baseline: 1.8681x; 1.2624x over previous
#include <cuda_runtime.h>
#include <cstdint>

#define BB 32
#define HH 56
#define HC 128
#define CC 256
#define PIX (HH*HH)          // 3136
#define EZ (BB*HC*PIX)       // 12845056
#define N1 (BB*PIX)          // 100352
#define OHH 112
#define OPIX (OHH*OHH)       // 12544
#define N2 (BB*OPIX)         // 401408

#define KP 264               // padded K stride (257 used)
#define KUSE 257
#define TPB 196              // 14x14 tiles per batch (F(4x4))
#define NT (BB*TPB)          // 6272 tiles

__device__ __align__(128) float g_z[EZ];            // conv1 out -> BEC output h
__device__ __align__(128) float g_U[36*KP*128];     // transformed weights [p][ic][oc]
__device__ __align__(128) float g_V[36*KP*NT];      // transformed inputs  [p][ic][T] (zero-init pads)
__device__ __align__(128) float g_M[36*128*NT];     // products [p][oc][T]
__device__ double g_d1[128*8*2];                    // BN1 partials
__device__ double g_sd2[256], g_qd2[256];           // BN2 atomic accumulators
__device__ float g_m1[HC], g_rs1[HC];

// ---------------------------------------------------------------------------
// Kernel A: weight transform  U = G g G^T  for F(4x4,3x3)
// ---------------------------------------------------------------------------
__global__ __launch_bounds__(256) void uT_kernel(const float* __restrict__ w1) {
  int i = blockIdx.x * 256 + threadIdx.x;
  if (i >= KUSE * 128) return;
  int oc = i & 127, ic = i >> 7;
  float g[3][3];
#pragma unroll
  for (int r = 0; r < 3; ++r)
#pragma unroll
    for (int c = 0; c < 3; ++c) g[r][c] = w1[oc * 2313 + ic * 9 + r * 3 + c];
  float t[6][3];
#pragma unroll
  for (int c = 0; c < 3; ++c) {
    t[0][c] = 0.25f * g[0][c];
    t[1][c] = (-1.f/6.f) * (g[0][c] + g[1][c] + g[2][c]);
    t[2][c] = (1.f/6.f) * (-g[0][c] + g[1][c] - g[2][c]);
    t[3][c] = (1.f/24.f) * g[0][c] + (1.f/12.f) * g[1][c] + (1.f/6.f) * g[2][c];
    t[4][c] = (1.f/24.f) * g[0][c] - (1.f/12.f) * g[1][c] + (1.f/6.f) * g[2][c];
    t[5][c] = g[2][c];
  }
  float u[6][6];
#pragma unroll
  for (int r = 0; r < 6; ++r) {
    u[r][0] = 0.25f * t[r][0];
    u[r][1] = (-1.f/6.f) * (t[r][0] + t[r][1] + t[r][2]);
    u[r][2] = (1.f/6.f) * (-t[r][0] + t[r][1] - t[r][2]);
    u[r][3] = (1.f/24.f) * t[r][0] + (1.f/12.f) * t[r][1] + (1.f/6.f) * t[r][2];
    u[r][4] = (1.f/24.f) * t[r][0] - (1.f/12.f) * t[r][1] + (1.f/6.f) * t[r][2];
    u[r][5] = t[r][2];
  }
#pragma unroll
  for (int p = 0; p < 36; ++p)
    g_U[(p * KP + ic) * 128 + oc] = u[p / 6][p % 6];
}

// ---------------------------------------------------------------------------
// Kernel B: input transform  V = B^T d B  per 4x4-output tile (6x6 input).
// grid (257, 32 b); one (b, ic) plane in smem (58x58 padded halo).
// ---------------------------------------------------------------------------
__global__ __launch_bounds__(256) void vT_kernel(
    const float* __restrict__ x, const float* __restrict__ nu) {
  __shared__ float sp[58 * 58];
  const int ic = blockIdx.x, b = blockIdx.y, t = threadIdx.x;
  for (int i = t; i < 58 * 58; i += 256) sp[i] = 0.f;
  __syncthreads();
  if (ic < 256) {
    const float* xp = x + ((long)b * 256 + ic) * PIX;
    for (int i = t; i < PIX; i += 256) {
      int r = i / 56, c = i - r * 56;
      sp[(r + 1) * 58 + c + 1] = xp[i];
    }
  } else {
    const float nf = nu[0] * 0.5f;
    for (int i = t; i < PIX; i += 256) {
      int r = i / 56, c = i - r * 56;
      sp[(r + 1) * 58 + c + 1] = nf;
    }
  }
  __syncthreads();

  const int base = ic * NT + b * TPB;
  for (int tile = t; tile < TPB; tile += 256) {
    const int ty = tile / 14, tx = tile - ty * 14;
    float d[6][6];
#pragma unroll
    for (int r = 0; r < 6; ++r)
#pragma unroll
      for (int c = 0; c < 6; ++c) d[r][c] = sp[(4 * ty + r) * 58 + 4 * tx + c];
    float td[6][6];
#pragma unroll
    for (int c = 0; c < 6; ++c) {
      td[0][c] = 4.f * d[0][c] - 5.f * d[2][c] + d[4][c];
      td[1][c] = -4.f * d[1][c] - 4.f * d[2][c] + d[3][c] + d[4][c];
      td[2][c] = 4.f * d[1][c] - 4.f * d[2][c] - d[3][c] + d[4][c];
      td[3][c] = -2.f * d[1][c] - d[2][c] + 2.f * d[3][c] + d[4][c];
      td[4][c] = 2.f * d[1][c] - d[2][c] - 2.f * d[3][c] + d[4][c];
      td[5][c] = 4.f * d[1][c] - 5.f * d[3][c] + d[5][c];
    }
    float v[6][6];
#pragma unroll
    for (int r = 0; r < 6; ++r) {
      v[r][0] = 4.f * td[r][0] - 5.f * td[r][2] + td[r][4];
      v[r][1] = -4.f * td[r][1] - 4.f * td[r][2] + td[r][3] + td[r][4];
      v[r][2] = 4.f * td[r][1] - 4.f * td[r][2] - td[r][3] + td[r][4];
      v[r][3] = -2.f * td[r][1] - td[r][2] + 2.f * td[r][3] + td[r][4];
      v[r][4] = 2.f * td[r][1] - td[r][2] - 2.f * td[r][3] + td[r][4];
      v[r][5] = 4.f * td[r][1] - 5.f * td[r][3] + td[r][5];
    }
#pragma unroll
    for (int p = 0; p < 36; ++p)
      g_V[p * (KP * NT) + base + tile] = v[p / 6][p % 6];
  }
}

// ---------------------------------------------------------------------------
// Kernel C: 36 batched GEMMs  M_p[128 oc][NT] = U_p[128][K=257] * V_p[257][NT].
// 32 full chunks of 8 (k 0..255) + single peeled step k=256.
// ---------------------------------------------------------------------------
__global__ __launch_bounds__(256) void wgemm_kernel() {
  __shared__ float sU[2][8 * 128];
  __shared__ float sV[2][8 * 128];
  const int t = threadIdx.x;
  const int og = t >> 4, tg = t & 15;
  const int p = blockIdx.y;
  const int Tb = blockIdx.x * 128;
  const int kr = t >> 5, c4 = (t & 31) * 4;

  const float* Ug = g_U + p * (KP * 128);
  const float* Vg = g_V + (long)p * (KP * NT);

  {
    float4 u = *(const float4*)&Ug[kr * 128 + c4];
    float4 v = *(const float4*)&Vg[kr * NT + Tb + c4];
    *(float4*)&sU[0][kr * 128 + c4] = u;
    *(float4*)&sV[0][kr * 128 + c4] = v;
  }
  __syncthreads();

  float acc[64];
#pragma unroll
  for (int i = 0; i < 64; ++i) acc[i] = 0.f;

  float4 pu, pv;
  for (int ch = 0; ch < 32; ++ch) {
    const int cur = ch & 1, nxt = cur ^ 1;
    {
      const int kn = ch * 8 + 8 + kr;   // rows 8..263 (257+ zero-init, unused)
      pu = *(const float4*)&Ug[kn * 128 + c4];
      pv = *(const float4*)&Vg[kn * NT + Tb + c4];
    }
#pragma unroll
    for (int k = 0; k < 8; ++k) {
      const float4 ua = *(const float4*)&sU[cur][k * 128 + og * 8];
      const float4 ub = *(const float4*)&sU[cur][k * 128 + og * 8 + 4];
      const float4 va = *(const float4*)&sV[cur][k * 128 + tg * 8];
      const float4 vb = *(const float4*)&sV[cur][k * 128 + tg * 8 + 4];
      const float uu[8] = {ua.x, ua.y, ua.z, ua.w, ub.x, ub.y, ub.z, ub.w};
      const float vv[8] = {va.x, va.y, va.z, va.w, vb.x, vb.y, vb.z, vb.w};
#pragma unroll
      for (int j = 0; j < 8; ++j)
#pragma unroll
        for (int i = 0; i < 8; ++i) acc[j * 8 + i] += uu[j] * vv[i];
    }
    *(float4*)&sU[nxt][kr * 128 + c4] = pu;
    *(float4*)&sV[nxt][kr * 128 + c4] = pv;
    __syncthreads();
  }
  // peeled final step: k = 256 (buffer 0 holds rows 256..263)
  {
    const float4 ua = *(const float4*)&sU[0][og * 8];
    const float4 ub = *(const float4*)&sU[0][og * 8 + 4];
    const float4 va = *(const float4*)&sV[0][tg * 8];
    const float4 vb = *(const float4*)&sV[0][tg * 8 + 4];
    const float uu[8] = {ua.x, ua.y, ua.z, ua.w, ub.x, ub.y, ub.z, ub.w};
    const float vv[8] = {va.x, va.y, va.z, va.w, vb.x, vb.y, vb.z, vb.w};
#pragma unroll
    for (int j = 0; j < 8; ++j)
#pragma unroll
      for (int i = 0; i < 8; ++i) acc[j * 8 + i] += uu[j] * vv[i];
  }

#pragma unroll
  for (int j = 0; j < 8; ++j) {
    float* dst = g_M + ((long)p * 128 + og * 8 + j) * NT + Tb + tg * 8;
    ((float4*)dst)[0] = make_float4(acc[j*8+0], acc[j*8+1], acc[j*8+2], acc[j*8+3]);
    ((float4*)dst)[1] = make_float4(acc[j*8+4], acc[j*8+5], acc[j*8+6], acc[j*8+7]);
  }
}

// ---------------------------------------------------------------------------
// Kernel D: output transform  Y = A^T M A  (+bias) -> g_z   (4x4 outputs)
// ---------------------------------------------------------------------------
__global__ __launch_bounds__(256) void oT_kernel(const float* __restrict__ b1) {
  const int i = blockIdx.x * 256 + threadIdx.x;
  const int tile = i % TPB;
  const int boc = i / TPB;
  const int oc = boc & 127, b = boc >> 7;
  const int Ti = b * TPB + tile;

  float m[6][6];
#pragma unroll
  for (int p = 0; p < 36; ++p)
    m[p / 6][p % 6] = g_M[((long)p * 128 + oc) * NT + Ti];

  float s[4][6];
#pragma unroll
  for (int c = 0; c < 6; ++c) {
    s[0][c] = m[0][c] + m[1][c] + m[2][c] + m[3][c] + m[4][c];
    s[1][c] = m[1][c] - m[2][c] + 2.f * m[3][c] - 2.f * m[4][c];
    s[2][c] = m[1][c] + m[2][c] + 4.f * m[3][c] + 4.f * m[4][c];
    s[3][c] = m[1][c] - m[2][c] + 8.f * m[3][c] - 8.f * m[4][c] + m[5][c];
  }
  const float bb = b1[oc];
  const int ty = tile / 14, tx = tile - ty * 14;
  float* dst = g_z + ((b * 128 + oc) * HH + 4 * ty) * HH + 4 * tx;
#pragma unroll
  for (int r = 0; r < 4; ++r) {
    float y0 = s[r][0] + s[r][1] + s[r][2] + s[r][3] + s[r][4] + bb;
    float y1 = s[r][1] - s[r][2] + 2.f * s[r][3] - 2.f * s[r][4] + bb;
    float y2 = s[r][1] + s[r][2] + 4.f * s[r][3] + 4.f * s[r][4] + bb;
    float y3 = s[r][1] - s[r][2] + 8.f * s[r][3] - 8.f * s[r][4] + s[r][5] + bb;
    *(float4*)(dst + r * HH) = make_float4(y0, y1, y2, y3);
  }
}

// ---------------------------------------------------------------------------
// Kernel 2a: BN1 partial stats — grid (128 ch, 8 slices)
// ---------------------------------------------------------------------------
__global__ __launch_bounds__(256) void stats1a_kernel() {
  const int c = blockIdx.x, sl = blockIdx.y, t = threadIdx.x;
  double s = 0.0, q = 0.0;
  for (int bb = sl * 4; bb < sl * 4 + 4; ++bb) {
    const float4* p = (const float4*)(g_z + (bb * 128 + c) * PIX);
    for (int i = t; i < PIX / 4; i += 256) {
      float4 v = p[i];
      s += (double)v.x + v.y + v.z + v.w;
      q += (double)v.x * v.x + (double)v.y * v.y +
           (double)v.z * v.z + (double)v.w * v.w;
    }
  }
  __shared__ double ss[256], sq[256];
  ss[t] = s; sq[t] = q;
  __syncthreads();
  for (int o = 128; o > 0; o >>= 1) {
    if (t < o) { ss[t] += ss[t + o]; sq[t] += sq[t + o]; }
    __syncthreads();
  }
  if (t == 0) {
    g_d1[(c * 8 + sl) * 2 + 0] = ss[0];
    g_d1[(c * 8 + sl) * 2 + 1] = sq[0];
  }
}

__global__ __launch_bounds__(128) void reduce1_kernel() {
  const int c = threadIdx.x;
  double s = 0.0, q = 0.0;
#pragma unroll
  for (int sl = 0; sl < 8; ++sl) {
    s += g_d1[(c * 8 + sl) * 2 + 0];
    q += g_d1[(c * 8 + sl) * 2 + 1];
  }
  double m   = s / N1;
  double var = q / N1 - m * m;
  g_m1[c]  = (float)m;
  g_rs1[c] = rsqrtf((float)var + 1e-5f);
}

// zero BN2 accumulators (before dec each replay)
__global__ __launch_bounds__(512) void zero2_kernel() {
  const int t = threadIdx.x;
  if (t < 256) { g_sd2[t] = 0.0; g_qd2[t] = 0.0; }
}

// ---------------------------------------------------------------------------
// Threefry2x32, key (0,42), partitionable draw: x0=0, x1=j, out = o0^o1.
// ---------------------------------------------------------------------------
__device__ __forceinline__ unsigned tf_xor(unsigned j) {
  const unsigned ks0 = 0u, ks1 = 42u, ks2 = 0x1BD11BDAu ^ 42u;
  unsigned x0 = 0u + ks0;
  unsigned x1 = j  + ks1;
#define TFRND(r) { x0 += x1; x1 = __funnelshift_l(x1, x1, r); x1 ^= x0; }
  TFRND(13) TFRND(15) TFRND(26) TFRND(6)
  x0 += ks1; x1 += ks2 + 1u;
  TFRND(17) TFRND(29) TFRND(16) TFRND(24)
  x0 += ks2; x1 += ks0 + 2u;
  TFRND(13) TFRND(15) TFRND(26) TFRND(6)
  x0 += ks0; x1 += ks1 + 3u;
  TFRND(17) TFRND(29) TFRND(16) TFRND(24)
  x0 += ks1; x1 += ks2 + 4u;
  TFRND(13) TFRND(15) TFRND(26) TFRND(6)
  x0 += ks2; x1 += ks0 + 5u;
#undef TFRND
  return x0 ^ x1;
}

// ---------------------------------------------------------------------------
// Kernel 3: BN1 apply + sigmoid + quantize + BEC (in place on g_z)
// ---------------------------------------------------------------------------
__global__ __launch_bounds__(256) void bec_kernel(
    const float* __restrict__ nu, const float* __restrict__ g1,
    const float* __restrict__ be1) {
  const int e = blockIdx.x * 256 + threadIdx.x;
  const int c = (e / PIX) & 127;
  const float z = g_z[e];
  float tt = (z - g_m1[c]) * g_rs1[c] * g1[c] + be1[c];
  float s  = 0.5f * tanhf(0.5f * tt) + 0.5f;
  float r  = rintf(s * 256.0f);
  if (r >= 256.0f) r -= 256.0f;
  const unsigned xb = (unsigned)r;

  const float q = 1.0f - nu[0] * 0.5f;
  unsigned mask = 0u;
#pragma unroll
  for (int k = 0; k < 8; ++k) {
    unsigned bits = tf_xor((unsigned)(k * EZ + e));
    float u = __uint_as_float((bits >> 9) | 0x3f800000u) - 1.0f;
    if (u < q) mask |= (1u << k);
  }
  float outv = ((float)(xb & mask) + (255.0f - (float)mask) / 2.0f) / 255.0f;
  g_z[e] = outv;
}

// ---------------------------------------------------------------------------
// Kernel 4: ConvTranspose2d(k2,s2) 4-tap GEMM + FUSED BN2 partial stats.
// ---------------------------------------------------------------------------
__global__ __launch_bounds__(256) void dec_kernel(
    const float* __restrict__ w4, const float* __restrict__ b4,
    float* __restrict__ out) {
  __shared__ float4 ws4[16 * 64];
  __shared__ float4 hs4[16 * 16];
  const int t = threadIdx.x;
  const int bp = blockIdx.x;
  const int b = bp / 49;
  const int pixb = (bp % 49) * 64;
  const int cb = blockIdx.y * 64;
  const int pgrp = t & 7;
  const int cgrp = t >> 3;

  float acc[64];
#pragma unroll
  for (int i = 0; i < 64; ++i) acc[i] = 0.f;

  const float4* w44 = (const float4*)w4;
  const float4* gz4 = (const float4*)g_z;

  for (int hc0 = 0; hc0 < 128; hc0 += 16) {
    __syncthreads();
#pragma unroll
    for (int i = 0; i < 4; ++i) {
      int idx = t + i * 256;
      int hh = idx >> 6, cl = idx & 63;
      ws4[idx] = w44[(hc0 + hh) * 256 + cb + cl];
    }
    {
      int hh = t >> 4, p4 = t & 15;
      hs4[t] = gz4[((b * 128 + hc0 + hh) * PIX + pixb) / 4 + p4];
    }
    __syncthreads();
#pragma unroll
    for (int hh = 0; hh < 16; ++hh) {
      const float4 h0 = hs4[hh * 16 + pgrp * 2];
      const float4 h1 = hs4[hh * 16 + pgrp * 2 + 1];
      const float4 wa = ws4[hh * 64 + cgrp * 2];
      const float4 wb = ws4[hh * 64 + cgrp * 2 + 1];
      const float hv[8] = {h0.x, h0.y, h0.z, h0.w, h1.x, h1.y, h1.z, h1.w};
#pragma unroll
      for (int pp = 0; pp < 8; ++pp) {
        acc[pp * 4 + 0] += hv[pp] * wa.x;
        acc[pp * 4 + 1] += hv[pp] * wa.y;
        acc[pp * 4 + 2] += hv[pp] * wa.z;
        acc[pp * 4 + 3] += hv[pp] * wa.w;
        acc[32 + pp * 4 + 0] += hv[pp] * wb.x;
        acc[32 + pp * 4 + 1] += hv[pp] * wb.y;
        acc[32 + pp * 4 + 2] += hv[pp] * wb.z;
        acc[32 + pp * 4 + 3] += hv[pp] * wb.w;
      }
    }
  }

  float sums[2] = {0.f, 0.f}, sumq[2] = {0.f, 0.f};
#pragma unroll
  for (int cc = 0; cc < 2; ++cc) {
    const int c = cb + cgrp * 2 + cc;
    const float bb = b4[c];
#pragma unroll
    for (int pp = 0; pp < 8; ++pp) {
      const int pix = pixb + pgrp * 8 + pp;
      const int ih = pix / HH, iw = pix % HH;
      float* dst = out + ((b * 256 + c) * OHH + 2 * ih) * OHH + 2 * iw;
      float v0 = acc[cc * 32 + pp * 4 + 0] + bb;
      float v1 = acc[cc * 32 + pp * 4 + 1] + bb;
      float v2 = acc[cc * 32 + pp * 4 + 2] + bb;
      float v3 = acc[cc * 32 + pp * 4 + 3] + bb;
      *(float2*)dst = make_float2(v0, v1);
      *(float2*)(dst + OHH) = make_float2(v2, v3);
      sums[cc] += v0 + v1 + v2 + v3;
      sumq[cc] += v0 * v0 + v1 * v1 + v2 * v2 + v3 * v3;
    }
  }
  // reduce over the 8 lanes sharing (cgrp) — consecutive lanes in warp
#pragma unroll
  for (int off = 1; off < 8; off <<= 1) {
    sums[0] += __shfl_xor_sync(0xffffffffu, sums[0], off);
    sumq[0] += __shfl_xor_sync(0xffffffffu, sumq[0], off);
    sums[1] += __shfl_xor_sync(0xffffffffu, sums[1], off);
    sumq[1] += __shfl_xor_sync(0xffffffffu, sumq[1], off);
  }
  if (pgrp == 0) {
    const int c0 = cb + cgrp * 2;
    atomicAdd(&g_sd2[c0],     (double)sums[0]);
    atomicAdd(&g_qd2[c0],     (double)sumq[0]);
    atomicAdd(&g_sd2[c0 + 1], (double)sums[1]);
    atomicAdd(&g_qd2[c0 + 1], (double)sumq[1]);
  }
}

// ---------------------------------------------------------------------------
// Kernel 6: BN2 apply (stats inline from accumulators) + relu, in place
// ---------------------------------------------------------------------------
__global__ __launch_bounds__(256) void bn2_kernel(
    const float* __restrict__ g2, const float* __restrict__ be2,
    float* __restrict__ out) {
  const int i = blockIdx.x * 256 + threadIdx.x;
  const int c = (i / (OPIX / 4)) & 255;
  const double inv = 1.0 / (double)N2;
  const double md = g_sd2[c] * inv;
  const double var = g_qd2[c] * inv - md * md;
  const float m = (float)md;
  const float rs = rsqrtf((float)var + 1e-5f);
  float4 v = ((float4*)out)[i];
  const float gg = g2[c], bb = be2[c];
  v.x = fmaxf((v.x - m) * rs * gg + bb, 0.f);
  v.y = fmaxf((v.y - m) * rs * gg + bb, 0.f);
  v.z = fmaxf((v.z - m) * rs * gg + bb, 0.f);
  v.w = fmaxf((v.w - m) * rs * gg + bb, 0.f);
  ((float4*)out)[i] = v;
}

// ---------------------------------------------------------------------------
extern "C" void kernel_launch(void* const* d_in, const int* in_sizes, int n_in,
                              void* d_out, int out_size) {
  const float* x   = (const float*)d_in[0];
  const float* nu  = (const float*)d_in[1];
  const float* w1  = (const float*)d_in[2];
  const float* b1  = (const float*)d_in[3];
  const float* g1  = (const float*)d_in[4];
  const float* be1 = (const float*)d_in[5];
  const float* w4  = (const float*)d_in[6];
  const float* b4  = (const float*)d_in[7];
  const float* g2  = (const float*)d_in[8];
  const float* be2 = (const float*)d_in[9];
  float* out = (float*)d_out;

  uT_kernel<<<(KUSE * 128 + 255) / 256, 256>>>(w1);
  vT_kernel<<<dim3(KUSE, 32), 256>>>(x, nu);
  wgemm_kernel<<<dim3(NT / 128, 36), 256>>>();
  oT_kernel<<<(BB * 128 * TPB) / 256, 256>>>(b1);
  stats1a_kernel<<<dim3(128, 8), 256>>>();
  reduce1_kernel<<<1, 128>>>();
  zero2_kernel<<<1, 512>>>();
  bec_kernel<<<EZ / 256, 256>>>(nu, g1, be1);
  dec_kernel<<<dim3(32 * 49, 4), 256>>>(w4, b4, out);
  bn2_kernel<<<out_size / 4 / 256, 256>>>(g2, be2, out);
}